// round 1
// baseline (speedup 1.0000x reference)
#include <cuda_runtime.h>
#include <math.h>

// Problem constants
#define Bb     4
#define SEQ    2048
#define DIM    768
#define NH     12
#define DH     64
#define INNER  768
#define MROWS  (Bb * SEQ)   // 8192

// Scratch (module-static device memory; allocation-free)
__device__ float g_q[Bb * NH * SEQ * DH];     // [b][h][n][dh], pre-scaled by 1/8
__device__ float g_k[Bb * NH * SEQ * DH];
__device__ float g_v[Bb * NH * SEQ * DH];
__device__ float g_att[MROWS * INNER];        // attention output, [b*n][h*64+dh]

// ---------------------------------------------------------------------------
// Kernel 1: fused QKV projection.  C = X[8192,768] @ W[768,768], written into
// head-major layout [b][h][n][dh].  blockIdx.z selects Wq/Wk/Wv.
// Tiling: 64x64 tile, BK=16, 256 threads, 4x4 micro-tile.
// ---------------------------------------------------------------------------
__global__ void qkv_kernel(const float* __restrict__ x,
                           const float* __restrict__ Wq,
                           const float* __restrict__ Wk,
                           const float* __restrict__ Wv) {
    __shared__ float As[16][64];   // [k][m]
    __shared__ float Bs[16][64];   // [k][n]

    const float* W;
    float* outp;
    float scale;
    if (blockIdx.z == 0)      { W = Wq; outp = g_q; scale = 0.125f; }
    else if (blockIdx.z == 1) { W = Wk; outp = g_k; scale = 1.0f;   }
    else                      { W = Wv; outp = g_v; scale = 1.0f;   }

    const int bm = blockIdx.y * 64;
    const int bn = blockIdx.x * 64;
    const int t  = threadIdx.x;
    const int ty = t >> 4;          // 0..15
    const int tx = t & 15;          // 0..15

    // load mapping
    const int aRow = t >> 2;        // 0..63
    const int aCol = (t & 3) * 4;   // 0,4,8,12
    const int bRow = t >> 4;        // 0..15
    const int bCol = (t & 15) * 4;  // 0..60

    float acc[4][4];
#pragma unroll
    for (int i = 0; i < 4; i++)
#pragma unroll
        for (int j = 0; j < 4; j++) acc[i][j] = 0.0f;

    for (int k0 = 0; k0 < DIM; k0 += 16) {
        float4 av = *(const float4*)&x[(size_t)(bm + aRow) * DIM + k0 + aCol];
        float4 bv = *(const float4*)&W[(size_t)(k0 + bRow) * INNER + bn + bCol];
        As[aCol + 0][aRow] = av.x;
        As[aCol + 1][aRow] = av.y;
        As[aCol + 2][aRow] = av.z;
        As[aCol + 3][aRow] = av.w;
        *(float4*)&Bs[bRow][bCol] = bv;
        __syncthreads();

#pragma unroll
        for (int k = 0; k < 16; k++) {
            float4 a4 = *(const float4*)&As[k][ty * 4];
            float4 b4 = *(const float4*)&Bs[k][tx * 4];
            float a[4] = {a4.x, a4.y, a4.z, a4.w};
            float b[4] = {b4.x, b4.y, b4.z, b4.w};
#pragma unroll
            for (int i = 0; i < 4; i++)
#pragma unroll
                for (int j = 0; j < 4; j++) acc[i][j] += a[i] * b[j];
        }
        __syncthreads();
    }

    // epilogue: scatter into [b][h][n][dh]
#pragma unroll
    for (int i = 0; i < 4; i++) {
        const int row = bm + ty * 4 + i;
        const int bidx = row >> 11;       // row / 2048
        const int n    = row & 2047;
#pragma unroll
        for (int j = 0; j < 4; j++) {
            const int col = bn + tx * 4 + j;
            const int h   = col >> 6;
            const int dh  = col & 63;
            outp[((((size_t)bidx * NH + h) * SEQ) + n) * DH + dh] = acc[i][j] * scale;
        }
    }
}

// ---------------------------------------------------------------------------
// Kernel 2: flash attention.  One block per (qtile=64, h, b).  Streams 32
// K/V tiles of 64 rows, online softmax, O in registers (4x4 per thread).
// ---------------------------------------------------------------------------
#define QS_OFF   0
#define KS_OFF   (64 * 65)
#define VS_OFF   (2 * 64 * 65)
#define SS_OFF   (2 * 64 * 65 + 64 * 64)
#define M_OFF    (SS_OFF + 64 * 65)
#define L_OFF    (M_OFF + 64)
#define RS_OFF   (L_OFF + 64)
#define FLASH_SMEM_FLOATS (RS_OFF + 64)

__global__ void flash_kernel() {
    extern __shared__ float sm[];
    float* Qs = sm + QS_OFF;   // [64][65]
    float* Ks = sm + KS_OFF;   // [64][65]
    float* Vs = sm + VS_OFF;   // [64][64]
    float* Ss = sm + SS_OFF;   // [64][65]
    float* mrow = sm + M_OFF;
    float* lrow = sm + L_OFF;
    float* rs   = sm + RS_OFF;

    const int qt = blockIdx.x;
    const int h  = blockIdx.y;
    const int b  = blockIdx.z;
    const int t  = threadIdx.x;
    const int ty = t >> 4;
    const int tx = t & 15;

    const size_t head_base = ((size_t)b * NH + h) * SEQ * DH;
    const float* qbase = g_q + head_base + (size_t)qt * 64 * DH;
    const float* kbase = g_k + head_base;
    const float* vbase = g_v + head_base;

    // load Q tile (64x64) -> Qs [64][65]
#pragma unroll
    for (int i = 0; i < 4; i++) {
        const int lin = (t + i * 256) * 4;
        const int r = lin >> 6, d = lin & 63;
        float4 v4 = *(const float4*)&qbase[lin];
        Qs[r * 65 + d + 0] = v4.x;
        Qs[r * 65 + d + 1] = v4.y;
        Qs[r * 65 + d + 2] = v4.z;
        Qs[r * 65 + d + 3] = v4.w;
    }
    if (t < 64) { mrow[t] = -INFINITY; lrow[t] = 0.0f; }

    float o[4][4];
#pragma unroll
    for (int i = 0; i < 4; i++)
#pragma unroll
        for (int j = 0; j < 4; j++) o[i][j] = 0.0f;

    for (int kt = 0; kt < SEQ / 64; kt++) {
        __syncthreads();   // protect Ks/Vs from previous iteration's consumers
        // load K, V tiles
        const float* kt_base = kbase + (size_t)kt * 64 * DH;
        const float* vt_base = vbase + (size_t)kt * 64 * DH;
#pragma unroll
        for (int i = 0; i < 4; i++) {
            const int lin = (t + i * 256) * 4;
            const int r = lin >> 6, d = lin & 63;
            float4 v4 = *(const float4*)&kt_base[lin];
            Ks[r * 65 + d + 0] = v4.x;
            Ks[r * 65 + d + 1] = v4.y;
            Ks[r * 65 + d + 2] = v4.z;
            Ks[r * 65 + d + 3] = v4.w;
            *(float4*)&Vs[lin] = *(const float4*)&vt_base[lin];
        }
        __syncthreads();

        // S = Q @ K^T  (4x4 per thread)
        float s[4][4];
#pragma unroll
        for (int i = 0; i < 4; i++)
#pragma unroll
            for (int j = 0; j < 4; j++) s[i][j] = 0.0f;
#pragma unroll 8
        for (int d = 0; d < 64; d++) {
            float a[4], bf[4];
#pragma unroll
            for (int i = 0; i < 4; i++) a[i]  = Qs[(ty * 4 + i) * 65 + d];
#pragma unroll
            for (int j = 0; j < 4; j++) bf[j] = Ks[(tx * 4 + j) * 65 + d];
#pragma unroll
            for (int i = 0; i < 4; i++)
#pragma unroll
                for (int j = 0; j < 4; j++) s[i][j] += a[i] * bf[j];
        }
#pragma unroll
        for (int i = 0; i < 4; i++)
#pragma unroll
            for (int j = 0; j < 4; j++)
                Ss[(ty * 4 + i) * 65 + tx * 4 + j] = s[i][j];
        __syncthreads();

        // online softmax row stats (threads 0..63, one row each)
        if (t < 64) {
            const float mo = mrow[t];
            float mx = mo;
#pragma unroll 8
            for (int j = 0; j < 64; j++) mx = fmaxf(mx, Ss[t * 65 + j]);
            const float c = __expf(mo - mx);
            float sum = 0.0f;
#pragma unroll 8
            for (int j = 0; j < 64; j++) {
                const float p = __expf(Ss[t * 65 + j] - mx);
                Ss[t * 65 + j] = p;
                sum += p;
            }
            lrow[t] = lrow[t] * c + sum;
            mrow[t] = mx;
            rs[t] = c;
        }
        __syncthreads();

        // O = O * c + P @ V
#pragma unroll
        for (int i = 0; i < 4; i++) {
            const float c = rs[ty * 4 + i];
#pragma unroll
            for (int j = 0; j < 4; j++) o[i][j] *= c;
        }
#pragma unroll 4
        for (int j2 = 0; j2 < 64; j2++) {
            float p[4];
#pragma unroll
            for (int i = 0; i < 4; i++) p[i] = Ss[(ty * 4 + i) * 65 + j2];
            float4 v4 = *(const float4*)&Vs[j2 * 64 + tx * 4];
            float vv[4] = {v4.x, v4.y, v4.z, v4.w};
#pragma unroll
            for (int i = 0; i < 4; i++)
#pragma unroll
                for (int j = 0; j < 4; j++) o[i][j] += p[i] * vv[j];
        }
    }
    __syncthreads();

    // epilogue: normalize and write to g_att [b*n][h*64+dh]
#pragma unroll
    for (int i = 0; i < 4; i++) {
        const int r = ty * 4 + i;
        const float linv = 1.0f / lrow[r];
        const int n = qt * 64 + r;
        float* dst = &g_att[((size_t)b * SEQ + n) * INNER + h * 64 + tx * 4];
#pragma unroll
        for (int j = 0; j < 4; j++) dst[j] = o[i][j] * linv;
    }
}

// ---------------------------------------------------------------------------
// Kernel 3: output projection.  out = g_att[8192,768] @ Wp[768,768] + bp
// ---------------------------------------------------------------------------
__global__ void proj_kernel(const float* __restrict__ Wp,
                            const float* __restrict__ bp,
                            float* __restrict__ out) {
    __shared__ float As[16][64];
    __shared__ float Bs[16][64];

    const int bm = blockIdx.y * 64;
    const int bn = blockIdx.x * 64;
    const int t  = threadIdx.x;
    const int ty = t >> 4;
    const int tx = t & 15;

    const int aRow = t >> 2;
    const int aCol = (t & 3) * 4;
    const int bRow = t >> 4;
    const int bCol = (t & 15) * 4;

    float acc[4][4];
#pragma unroll
    for (int i = 0; i < 4; i++)
#pragma unroll
        for (int j = 0; j < 4; j++) acc[i][j] = 0.0f;

    for (int k0 = 0; k0 < INNER; k0 += 16) {
        float4 av = *(const float4*)&g_att[(size_t)(bm + aRow) * INNER + k0 + aCol];
        float4 bv = *(const float4*)&Wp[(size_t)(k0 + bRow) * DIM + bn + bCol];
        As[aCol + 0][aRow] = av.x;
        As[aCol + 1][aRow] = av.y;
        As[aCol + 2][aRow] = av.z;
        As[aCol + 3][aRow] = av.w;
        *(float4*)&Bs[bRow][bCol] = bv;
        __syncthreads();

#pragma unroll
        for (int k = 0; k < 16; k++) {
            float4 a4 = *(const float4*)&As[k][ty * 4];
            float4 b4 = *(const float4*)&Bs[k][tx * 4];
            float a[4] = {a4.x, a4.y, a4.z, a4.w};
            float b[4] = {b4.x, b4.y, b4.z, b4.w};
#pragma unroll
            for (int i = 0; i < 4; i++)
#pragma unroll
                for (int j = 0; j < 4; j++) acc[i][j] += a[i] * b[j];
        }
        __syncthreads();
    }

#pragma unroll
    for (int i = 0; i < 4; i++) {
        const int row = bm + ty * 4 + i;
#pragma unroll
        for (int j = 0; j < 4; j++) {
            const int col = bn + tx * 4 + j;
            out[(size_t)row * DIM + col] = acc[i][j] + bp[col];
        }
    }
}

// ---------------------------------------------------------------------------
extern "C" void kernel_launch(void* const* d_in, const int* in_sizes, int n_in,
                              void* d_out, int out_size) {
    const float* x  = (const float*)d_in[0];
    const float* Wq = (const float*)d_in[1];
    const float* Wk = (const float*)d_in[2];
    const float* Wv = (const float*)d_in[3];
    const float* Wp = (const float*)d_in[4];
    const float* bp = (const float*)d_in[5];
    float* out = (float*)d_out;

    // 1) QKV projections
    dim3 g1(INNER / 64, MROWS / 64, 3);
    qkv_kernel<<<g1, 256>>>(x, Wq, Wk, Wv);

    // 2) flash attention
    const int smem_bytes = FLASH_SMEM_FLOATS * (int)sizeof(float);
    cudaFuncSetAttribute(flash_kernel,
                         cudaFuncAttributeMaxDynamicSharedMemorySize, smem_bytes);
    flash_kernel<<<dim3(SEQ / 64, NH, Bb), 256, smem_bytes>>>();

    // 3) output projection + bias
    proj_kernel<<<dim3(DIM / 64, MROWS / 64), 256>>>(Wp, bp, out);
}

// round 3
// speedup vs baseline: 3.2312x; 3.2312x over previous
#include <cuda_runtime.h>
#include <math.h>
#include <stdint.h>

// Problem constants
#define Bb     4
#define SEQ    2048
#define DIM    768
#define NH     12
#define DH     64
#define INNER  768
#define MROWS  (Bb * SEQ)   // 8192

// Scratch (module-static device memory; allocation-free)
__device__ float g_q[Bb * NH * SEQ * DH];     // [b][h][n][dh], pre-scaled by 1/8
__device__ float g_k[Bb * NH * SEQ * DH];
__device__ float g_v[Bb * NH * SEQ * DH];
__device__ float g_att[MROWS * INNER];        // attention output, [b*n][h*64+dh]

// ---------------------------------------------------------------------------
// Helpers: tf32 rounding + m16n8k8 tf32 tensor-core MMA
// ---------------------------------------------------------------------------
__device__ __forceinline__ float tf32r(float x) {
    uint32_t u;
    asm("cvt.rna.tf32.f32 %0, %1;" : "=r"(u) : "f"(x));
    return __uint_as_float(u);
}

__device__ __forceinline__ void mma_tf32(float d[4], const uint32_t a[4],
                                         const uint32_t b[2]) {
    asm volatile(
        "mma.sync.aligned.m16n8k8.row.col.f32.tf32.tf32.f32 "
        "{%0,%1,%2,%3}, {%4,%5,%6,%7}, {%8,%9}, {%0,%1,%2,%3};"
        : "+f"(d[0]), "+f"(d[1]), "+f"(d[2]), "+f"(d[3])
        : "r"(a[0]), "r"(a[1]), "r"(a[2]), "r"(a[3]), "r"(b[0]), "r"(b[1]));
}

// ---------------------------------------------------------------------------
// Kernel 1: fused QKV projection via tf32 MMA.
// C = X[8192,768] @ W[768,768], scattered into head-major [b][h][n][dh].
// BM=128, BN=64, BK=32, 256 threads, warp grid 4(m) x 2(n), warp tile 32x32.
// ---------------------------------------------------------------------------
#define AS_STRIDE 36   // 36 mod 32 = 4 -> quad (row=lane/4, col=lane%4) conflict-free
#define BS_STRIDE 72   // 72 mod 32 = 8 -> quad (row=lane%4, col=lane/4) conflict-free

__global__ __launch_bounds__(256, 2) void qkv_kernel(const float* __restrict__ x,
                                                     const float* __restrict__ Wq,
                                                     const float* __restrict__ Wk,
                                                     const float* __restrict__ Wv) {
    __shared__ float As[128 * AS_STRIDE];
    __shared__ float Bs[32 * BS_STRIDE];
    const uint32_t* Asu = (const uint32_t*)As;
    const uint32_t* Bsu = (const uint32_t*)Bs;

    const float* W;
    float* outp;
    float scale;
    if (blockIdx.z == 0)      { W = Wq; outp = g_q; scale = 0.125f; }
    else if (blockIdx.z == 1) { W = Wk; outp = g_k; scale = 1.0f;   }
    else                      { W = Wv; outp = g_v; scale = 1.0f;   }

    const int bm = blockIdx.y * 128;
    const int bn = blockIdx.x * 64;
    const int t  = threadIdx.x;
    const int warp = t >> 5;
    const int lane = t & 31;
    const int wm = warp >> 1;        // 0..3
    const int wn = warp & 1;         // 0..1
    const int m_base = wm * 32;
    const int n_base = wn * 32;
    const int qr = lane >> 2;        // 0..7
    const int qc = lane & 3;         // 0..3

    float acc[2][4][4];
#pragma unroll
    for (int mt = 0; mt < 2; mt++)
#pragma unroll
        for (int j = 0; j < 4; j++)
#pragma unroll
            for (int e = 0; e < 4; e++) acc[mt][j][e] = 0.0f;

    for (int k0 = 0; k0 < DIM; k0 += 32) {
        __syncthreads();
        // Fill As: 128x32 (tf32-rounded)
#pragma unroll
        for (int i = 0; i < 4; i++) {
            const int lin = t + i * 256;          // float4 index
            const int row = lin >> 3;
            const int col = (lin & 7) * 4;
            float4 v = *(const float4*)&x[(size_t)(bm + row) * DIM + k0 + col];
            v.x = tf32r(v.x); v.y = tf32r(v.y); v.z = tf32r(v.z); v.w = tf32r(v.w);
            *(float4*)&As[row * AS_STRIDE + col] = v;
        }
        // Fill Bs: 32x64 (tf32-rounded)
#pragma unroll
        for (int i = 0; i < 2; i++) {
            const int lin = t + i * 256;
            const int row = lin >> 4;
            const int col = (lin & 15) * 4;
            float4 v = *(const float4*)&W[(size_t)(k0 + row) * INNER + bn + col];
            v.x = tf32r(v.x); v.y = tf32r(v.y); v.z = tf32r(v.z); v.w = tf32r(v.w);
            *(float4*)&Bs[row * BS_STRIDE + col] = v;
        }
        __syncthreads();

#pragma unroll
        for (int ks = 0; ks < 4; ks++) {
            const int kk = ks * 8;
            uint32_t a[2][4];
#pragma unroll
            for (int mt = 0; mt < 2; mt++) {
                const int row = m_base + mt * 16 + qr;
                a[mt][0] = Asu[row * AS_STRIDE + kk + qc];
                a[mt][1] = Asu[(row + 8) * AS_STRIDE + kk + qc];
                a[mt][2] = Asu[row * AS_STRIDE + kk + 4 + qc];
                a[mt][3] = Asu[(row + 8) * AS_STRIDE + kk + 4 + qc];
            }
            uint32_t b[4][2];
#pragma unroll
            for (int j = 0; j < 4; j++) {
                const int col = n_base + j * 8 + qr;
                b[j][0] = Bsu[(kk + qc) * BS_STRIDE + col];
                b[j][1] = Bsu[(kk + 4 + qc) * BS_STRIDE + col];
            }
#pragma unroll
            for (int mt = 0; mt < 2; mt++)
#pragma unroll
                for (int j = 0; j < 4; j++) mma_tf32(acc[mt][j], a[mt], b[j]);
        }
    }

    // Epilogue: scatter C-frag into [b][h][n][dh]
#pragma unroll
    for (int mt = 0; mt < 2; mt++) {
#pragma unroll
        for (int j = 0; j < 4; j++) {
#pragma unroll
            for (int e = 0; e < 4; e++) {
                const int row = bm + m_base + mt * 16 + qr + (e >= 2 ? 8 : 0);
                const int col = bn + n_base + j * 8 + 2 * qc + (e & 1);
                const int bidx = row >> 11;
                const int n    = row & 2047;
                const int h    = col >> 6;
                const int dh   = col & 63;
                outp[((((size_t)bidx * NH + h) * SEQ) + n) * DH + dh] =
                    acc[mt][j][e] * scale;
            }
        }
    }
}

// ---------------------------------------------------------------------------
// Kernel 2: flash attention with tf32 MMA.
// 128 queries/block, 8 warps, warp w owns query rows [w*16, w*16+16).
// KV streamed in 64-key tiles. Q frags persistent in registers.
// smem strides: 68 (quad row/lane%4-col pattern), 72 (quad col pattern).
// ---------------------------------------------------------------------------
#define KS_STRIDE 68
#define VS_STRIDE 72
#define PS_STRIDE 68
#define KS_OFF 0
#define VS_OFF (64 * KS_STRIDE)                  // 4352
#define PS_OFF (64 * KS_STRIDE + 64 * VS_STRIDE) // 8960
#define FLASH_SMEM_FLOATS (PS_OFF + 128 * PS_STRIDE)

__global__ __launch_bounds__(256, 2) void flash_kernel() {
    extern __shared__ float sm[];
    float* Ks = sm + KS_OFF;
    float* Vs = sm + VS_OFF;
    float* Ps = sm + PS_OFF;
    const uint32_t* Ksu = (const uint32_t*)Ks;
    const uint32_t* Vsu = (const uint32_t*)Vs;
    const uint32_t* Psu = (const uint32_t*)Ps;

    const int qt = blockIdx.x;     // 0..15 (128-query tiles)
    const int h  = blockIdx.y;
    const int b  = blockIdx.z;
    const int t  = threadIdx.x;
    const int warp = t >> 5;
    const int lane = t & 31;
    const int qr = lane >> 2;
    const int qc = lane & 3;
    const int wrow = warp * 16;    // warp's first query row (local)

    const size_t head_base = ((size_t)b * NH + h) * SEQ * DH;
    const float* qbase = g_q + head_base + (size_t)qt * 128 * DH;
    const float* kbase = g_k + head_base;
    const float* vbase = g_v + head_base;

    // Stage Q tile (128x64, tf32-rounded) into Ps, then build register frags
#pragma unroll
    for (int i = 0; i < 8; i++) {
        const int lin = (t + i * 256) * 4;
        const int row = lin >> 6;
        const int d   = lin & 63;
        float4 v = *(const float4*)&qbase[lin];
        v.x = tf32r(v.x); v.y = tf32r(v.y); v.z = tf32r(v.z); v.w = tf32r(v.w);
        *(float4*)&Ps[row * PS_STRIDE + d] = v;
    }
    __syncthreads();

    uint32_t qf[8][4];
#pragma unroll
    for (int ks = 0; ks < 8; ks++) {
        const int kk = ks * 8;
        qf[ks][0] = Psu[(wrow + qr) * PS_STRIDE + kk + qc];
        qf[ks][1] = Psu[(wrow + qr + 8) * PS_STRIDE + kk + qc];
        qf[ks][2] = Psu[(wrow + qr) * PS_STRIDE + kk + 4 + qc];
        qf[ks][3] = Psu[(wrow + qr + 8) * PS_STRIDE + kk + 4 + qc];
    }

    float o[8][4];
#pragma unroll
    for (int j = 0; j < 8; j++)
#pragma unroll
        for (int e = 0; e < 4; e++) o[j][e] = 0.0f;
    float m_lo = -INFINITY, m_hi = -INFINITY, l_lo = 0.0f, l_hi = 0.0f;

    for (int kt = 0; kt < SEQ / 64; kt++) {
        __syncthreads();   // protect Ks/Vs/Ps from previous iteration readers
        const float* kt_base = kbase + (size_t)kt * 64 * DH;
        const float* vt_base = vbase + (size_t)kt * 64 * DH;
#pragma unroll
        for (int i = 0; i < 4; i++) {
            const int lin = (t + i * 256) * 4;
            const int row = lin >> 6;
            const int d   = lin & 63;
            float4 kv = *(const float4*)&kt_base[lin];
            kv.x = tf32r(kv.x); kv.y = tf32r(kv.y); kv.z = tf32r(kv.z); kv.w = tf32r(kv.w);
            *(float4*)&Ks[row * KS_STRIDE + d] = kv;
            float4 vv = *(const float4*)&vt_base[lin];
            vv.x = tf32r(vv.x); vv.y = tf32r(vv.y); vv.z = tf32r(vv.z); vv.w = tf32r(vv.w);
            *(float4*)&Vs[row * VS_STRIDE + d] = vv;
        }
        __syncthreads();

        // S = Q @ K^T : warp computes 16x64
        float s[8][4];
#pragma unroll
        for (int j = 0; j < 8; j++)
#pragma unroll
            for (int e = 0; e < 4; e++) s[j][e] = 0.0f;
#pragma unroll
        for (int ks = 0; ks < 8; ks++) {
            const int kk = ks * 8;
#pragma unroll
            for (int j = 0; j < 8; j++) {
                uint32_t bfr[2];
                bfr[0] = Ksu[(j * 8 + qr) * KS_STRIDE + kk + qc];
                bfr[1] = Ksu[(j * 8 + qr) * KS_STRIDE + kk + 4 + qc];
                mma_tf32(s[j], qf[ks], bfr);
            }
        }

        // Online softmax (rows fully owned by the warp; quad = lane^1, lane^2)
        float mx_lo = m_lo, mx_hi = m_hi;
#pragma unroll
        for (int j = 0; j < 8; j++) {
            mx_lo = fmaxf(mx_lo, fmaxf(s[j][0], s[j][1]));
            mx_hi = fmaxf(mx_hi, fmaxf(s[j][2], s[j][3]));
        }
        mx_lo = fmaxf(mx_lo, __shfl_xor_sync(0xffffffffu, mx_lo, 1));
        mx_lo = fmaxf(mx_lo, __shfl_xor_sync(0xffffffffu, mx_lo, 2));
        mx_hi = fmaxf(mx_hi, __shfl_xor_sync(0xffffffffu, mx_hi, 1));
        mx_hi = fmaxf(mx_hi, __shfl_xor_sync(0xffffffffu, mx_hi, 2));

        const float c_lo = __expf(m_lo - mx_lo);
        const float c_hi = __expf(m_hi - mx_hi);
        float sum_lo = 0.0f, sum_hi = 0.0f;
#pragma unroll
        for (int j = 0; j < 8; j++) {
            s[j][0] = __expf(s[j][0] - mx_lo);
            s[j][1] = __expf(s[j][1] - mx_lo);
            s[j][2] = __expf(s[j][2] - mx_hi);
            s[j][3] = __expf(s[j][3] - mx_hi);
            sum_lo += s[j][0] + s[j][1];
            sum_hi += s[j][2] + s[j][3];
        }
        sum_lo += __shfl_xor_sync(0xffffffffu, sum_lo, 1);
        sum_lo += __shfl_xor_sync(0xffffffffu, sum_lo, 2);
        sum_hi += __shfl_xor_sync(0xffffffffu, sum_hi, 1);
        sum_hi += __shfl_xor_sync(0xffffffffu, sum_hi, 2);
        l_lo = l_lo * c_lo + sum_lo;
        l_hi = l_hi * c_hi + sum_hi;
        m_lo = mx_lo;
        m_hi = mx_hi;

        // Rescale O accumulators
#pragma unroll
        for (int j = 0; j < 8; j++) {
            o[j][0] *= c_lo; o[j][1] *= c_lo;
            o[j][2] *= c_hi; o[j][3] *= c_hi;
        }

        // Store P (tf32-rounded) to smem for A-fragment reuse
#pragma unroll
        for (int j = 0; j < 8; j++) {
            const int col = j * 8 + 2 * qc;
            *(float2*)&Ps[(wrow + qr) * PS_STRIDE + col] =
                make_float2(tf32r(s[j][0]), tf32r(s[j][1]));
            *(float2*)&Ps[(wrow + qr + 8) * PS_STRIDE + col] =
                make_float2(tf32r(s[j][2]), tf32r(s[j][3]));
        }
        __syncwarp();   // warp reads only its own P rows

        // O += P @ V
#pragma unroll
        for (int ks = 0; ks < 8; ks++) {
            const int kk = ks * 8;
            uint32_t a[4];
            a[0] = Psu[(wrow + qr) * PS_STRIDE + kk + qc];
            a[1] = Psu[(wrow + qr + 8) * PS_STRIDE + kk + qc];
            a[2] = Psu[(wrow + qr) * PS_STRIDE + kk + 4 + qc];
            a[3] = Psu[(wrow + qr + 8) * PS_STRIDE + kk + 4 + qc];
#pragma unroll
            for (int j = 0; j < 8; j++) {
                uint32_t bfr[2];
                bfr[0] = Vsu[(kk + qc) * VS_STRIDE + j * 8 + qr];
                bfr[1] = Vsu[(kk + 4 + qc) * VS_STRIDE + j * 8 + qr];
                mma_tf32(o[j], a, bfr);
            }
        }
    }

    // Epilogue: normalize, write to g_att [b*n][h*64+dh]
    const float inv_lo = 1.0f / l_lo;
    const float inv_hi = 1.0f / l_hi;
    const int n_lo = qt * 128 + wrow + qr;
#pragma unroll
    for (int j = 0; j < 8; j++) {
        const int col = h * 64 + j * 8 + 2 * qc;
        *(float2*)&g_att[((size_t)b * SEQ + n_lo) * INNER + col] =
            make_float2(o[j][0] * inv_lo, o[j][1] * inv_lo);
        *(float2*)&g_att[((size_t)b * SEQ + n_lo + 8) * INNER + col] =
            make_float2(o[j][2] * inv_hi, o[j][3] * inv_hi);
    }
}

// ---------------------------------------------------------------------------
// Kernel 3: output projection via tf32 MMA.  out = g_att @ Wp + bp
// Same tiling as qkv_kernel.
// ---------------------------------------------------------------------------
__global__ __launch_bounds__(256, 2) void proj_kernel(const float* __restrict__ Wp,
                                                      const float* __restrict__ bp,
                                                      float* __restrict__ out) {
    __shared__ float As[128 * AS_STRIDE];
    __shared__ float Bs[32 * BS_STRIDE];
    const uint32_t* Asu = (const uint32_t*)As;
    const uint32_t* Bsu = (const uint32_t*)Bs;

    const int bm = blockIdx.y * 128;
    const int bn = blockIdx.x * 64;
    const int t  = threadIdx.x;
    const int warp = t >> 5;
    const int lane = t & 31;
    const int wm = warp >> 1;
    const int wn = warp & 1;
    const int m_base = wm * 32;
    const int n_base = wn * 32;
    const int qr = lane >> 2;
    const int qc = lane & 3;

    float acc[2][4][4];
#pragma unroll
    for (int mt = 0; mt < 2; mt++)
#pragma unroll
        for (int j = 0; j < 4; j++)
#pragma unroll
            for (int e = 0; e < 4; e++) acc[mt][j][e] = 0.0f;

    for (int k0 = 0; k0 < INNER; k0 += 32) {
        __syncthreads();
#pragma unroll
        for (int i = 0; i < 4; i++) {
            const int lin = t + i * 256;
            const int row = lin >> 3;
            const int col = (lin & 7) * 4;
            float4 v = *(const float4*)&g_att[(size_t)(bm + row) * INNER + k0 + col];
            v.x = tf32r(v.x); v.y = tf32r(v.y); v.z = tf32r(v.z); v.w = tf32r(v.w);
            *(float4*)&As[row * AS_STRIDE + col] = v;
        }
#pragma unroll
        for (int i = 0; i < 2; i++) {
            const int lin = t + i * 256;
            const int row = lin >> 4;
            const int col = (lin & 15) * 4;
            float4 v = *(const float4*)&Wp[(size_t)(k0 + row) * DIM + bn + col];
            v.x = tf32r(v.x); v.y = tf32r(v.y); v.z = tf32r(v.z); v.w = tf32r(v.w);
            *(float4*)&Bs[row * BS_STRIDE + col] = v;
        }
        __syncthreads();

#pragma unroll
        for (int ks = 0; ks < 4; ks++) {
            const int kk = ks * 8;
            uint32_t a[2][4];
#pragma unroll
            for (int mt = 0; mt < 2; mt++) {
                const int row = m_base + mt * 16 + qr;
                a[mt][0] = Asu[row * AS_STRIDE + kk + qc];
                a[mt][1] = Asu[(row + 8) * AS_STRIDE + kk + qc];
                a[mt][2] = Asu[row * AS_STRIDE + kk + 4 + qc];
                a[mt][3] = Asu[(row + 8) * AS_STRIDE + kk + 4 + qc];
            }
            uint32_t b[4][2];
#pragma unroll
            for (int j = 0; j < 4; j++) {
                const int col = n_base + j * 8 + qr;
                b[j][0] = Bsu[(kk + qc) * BS_STRIDE + col];
                b[j][1] = Bsu[(kk + 4 + qc) * BS_STRIDE + col];
            }
#pragma unroll
            for (int mt = 0; mt < 2; mt++)
#pragma unroll
                for (int j = 0; j < 4; j++) mma_tf32(acc[mt][j], a[mt], b[j]);
        }
    }

#pragma unroll
    for (int mt = 0; mt < 2; mt++) {
#pragma unroll
        for (int j = 0; j < 4; j++) {
            const int row0 = bm + m_base + mt * 16 + qr;
            const int col0 = bn + n_base + j * 8 + 2 * qc;
            out[(size_t)row0 * DIM + col0]       = acc[mt][j][0] + bp[col0];
            out[(size_t)row0 * DIM + col0 + 1]   = acc[mt][j][1] + bp[col0 + 1];
            out[(size_t)(row0 + 8) * DIM + col0]     = acc[mt][j][2] + bp[col0];
            out[(size_t)(row0 + 8) * DIM + col0 + 1] = acc[mt][j][3] + bp[col0 + 1];
        }
    }
}

// ---------------------------------------------------------------------------
extern "C" void kernel_launch(void* const* d_in, const int* in_sizes, int n_in,
                              void* d_out, int out_size) {
    const float* x  = (const float*)d_in[0];
    const float* Wq = (const float*)d_in[1];
    const float* Wk = (const float*)d_in[2];
    const float* Wv = (const float*)d_in[3];
    const float* Wp = (const float*)d_in[4];
    const float* bp = (const float*)d_in[5];
    float* out = (float*)d_out;

    // 1) QKV projections (tf32 MMA)
    qkv_kernel<<<dim3(INNER / 64, MROWS / 128, 3), 256>>>(x, Wq, Wk, Wv);

    // 2) flash attention (tf32 MMA)
    const int smem_bytes = FLASH_SMEM_FLOATS * (int)sizeof(float);
    cudaFuncSetAttribute(flash_kernel,
                         cudaFuncAttributeMaxDynamicSharedMemorySize, smem_bytes);
    flash_kernel<<<dim3(SEQ / 128, NH, Bb), 256, smem_bytes>>>();

    // 3) output projection + bias (tf32 MMA)
    proj_kernel<<<dim3(DIM / 64, MROWS / 128), 256>>>(Wp, bp, out);
}

// round 4
// speedup vs baseline: 3.9900x; 1.2348x over previous
#include <cuda_runtime.h>
#include <math.h>
#include <stdint.h>

// Problem constants
#define Bb     4
#define SEQ    2048
#define DIM    768
#define NH     12
#define DH     64
#define INNER  768
#define MROWS  (Bb * SEQ)   // 8192
#define NXF    (MROWS * DIM)      // 6291456 floats in x
#define NWF    (DIM * INNER)      // 589824 floats per weight

// Scratch (module-static device memory; allocation-free)
__device__ float g_x[NXF];                    // tf32-rounded x
__device__ float g_w[4 * NWF];                // tf32-rounded Wq,Wk,Wv,Wp
__device__ float g_q[Bb * NH * SEQ * DH];     // [b][h][n][dh], tf32, pre-scaled 1/8
__device__ float g_k[Bb * NH * SEQ * DH];
__device__ float g_v[Bb * NH * SEQ * DH];
__device__ float g_att[MROWS * INNER];        // attention out (tf32), [b*n][h*64+dh]

// ---------------------------------------------------------------------------
// Helpers
// ---------------------------------------------------------------------------
__device__ __forceinline__ float tf32r(float x) {
    uint32_t u;
    asm("cvt.rna.tf32.f32 %0, %1;" : "=r"(u) : "f"(x));
    return __uint_as_float(u);
}

__device__ __forceinline__ void mma_tf32(float d[4], const uint32_t a[4],
                                         const uint32_t b[2]) {
    asm volatile(
        "mma.sync.aligned.m16n8k8.row.col.f32.tf32.tf32.f32 "
        "{%0,%1,%2,%3}, {%4,%5,%6,%7}, {%8,%9}, {%0,%1,%2,%3};"
        : "+f"(d[0]), "+f"(d[1]), "+f"(d[2]), "+f"(d[3])
        : "r"(a[0]), "r"(a[1]), "r"(a[2]), "r"(a[3]), "r"(b[0]), "r"(b[1]));
}

__device__ __forceinline__ void cp16(uint32_t saddr, const void* gaddr) {
    asm volatile("cp.async.cg.shared.global [%0], [%1], 16;" :: "r"(saddr), "l"(gaddr));
}
#define CP_COMMIT()  asm volatile("cp.async.commit_group;")
#define CP_WAIT1()   asm volatile("cp.async.wait_group 1;" ::: "memory")
#define CP_WAIT0()   asm volatile("cp.async.wait_group 0;" ::: "memory")

// ---------------------------------------------------------------------------
// Kernel 0: round x and the 4 weight matrices to tf32 (elementwise, once).
// grid*block*4 == NXF + 4*NWF exactly (8448 blocks of 256).
// ---------------------------------------------------------------------------
__global__ void round_kernel(const float* __restrict__ x,
                             const float* __restrict__ Wq,
                             const float* __restrict__ Wk,
                             const float* __restrict__ Wv,
                             const float* __restrict__ Wp) {
    const int base = (blockIdx.x * 256 + threadIdx.x) * 4;
    if (base < NXF) {
        float4 v = *(const float4*)&x[base];
        v.x = tf32r(v.x); v.y = tf32r(v.y); v.z = tf32r(v.z); v.w = tf32r(v.w);
        *(float4*)&g_x[base] = v;
    } else {
        const int j = base - NXF;
        const int w = j / NWF;
        const int off = j - w * NWF;
        const float* src = (w == 0) ? Wq : (w == 1) ? Wk : (w == 2) ? Wv : Wp;
        float4 v = *(const float4*)&src[off];
        v.x = tf32r(v.x); v.y = tf32r(v.y); v.z = tf32r(v.z); v.w = tf32r(v.w);
        *(float4*)&g_w[w * NWF + off] = v;
    }
}

// ---------------------------------------------------------------------------
// GEMM smem geometry (qkv & proj): BM=128, BN=128, BK=32, 2-stage cp.async.
// As stage: 128 x 36 floats (stride 36 == 4 mod 32 -> A-frag conflict-free)
// Bs stage:  32 x 136 floats (stride 136 == 8 mod 32 -> B-frag conflict-free)
// ---------------------------------------------------------------------------
#define ASTRIDE   36
#define BSTRIDE   136
#define AS_STAGE  (128 * ASTRIDE)          // 4608 floats
#define BS_BASE   (2 * AS_STAGE)           // 9216
#define BS_STAGE  (32 * BSTRIDE)           // 4352
#define GEMM_SMEM_FLOATS (BS_BASE + 2 * BS_STAGE)   // 17920 -> 71680 B

__device__ __forceinline__ void gemm_fill(uint32_t su, int st, int k0,
                                          const float* __restrict__ gA, int bm,
                                          const float* __restrict__ gB, int bn,
                                          int t) {
#pragma unroll
    for (int i = 0; i < 4; i++) {
        const int lin = t + i * 256;
        const int row = lin >> 3;
        const int col = (lin & 7) * 4;
        cp16(su + (uint32_t)(st * AS_STAGE + row * ASTRIDE + col) * 4,
             &gA[(size_t)(bm + row) * DIM + k0 + col]);
    }
#pragma unroll
    for (int i = 0; i < 4; i++) {
        const int lin = t + i * 256;
        const int row = lin >> 5;
        const int col = (lin & 31) * 4;
        cp16(su + (uint32_t)(BS_BASE + st * BS_STAGE + row * BSTRIDE + col) * 4,
             &gB[(size_t)(k0 + row) * INNER + bn + col]);
    }
}

// Core compute of one BK=32 stage. acc[2][8][4], warp tile 32x64.
__device__ __forceinline__ void gemm_compute(const float* __restrict__ smf, int st,
                                             int m_base, int n_base, int qr, int qc,
                                             float acc[2][8][4]) {
    const uint32_t* A = (const uint32_t*)(smf + st * AS_STAGE);
    const uint32_t* Bm = (const uint32_t*)(smf + BS_BASE + st * BS_STAGE);
#pragma unroll
    for (int ks = 0; ks < 4; ks++) {
        const int kk = ks * 8;
        uint32_t a[2][4];
#pragma unroll
        for (int mt = 0; mt < 2; mt++) {
            const int row = m_base + mt * 16 + qr;
            a[mt][0] = A[row * ASTRIDE + kk + qc];
            a[mt][1] = A[(row + 8) * ASTRIDE + kk + qc];
            a[mt][2] = A[row * ASTRIDE + kk + 4 + qc];
            a[mt][3] = A[(row + 8) * ASTRIDE + kk + 4 + qc];
        }
#pragma unroll
        for (int j = 0; j < 8; j++) {
            uint32_t b[2];
            const int col = n_base + j * 8 + qr;
            b[0] = Bm[(kk + qc) * BSTRIDE + col];
            b[1] = Bm[(kk + 4 + qc) * BSTRIDE + col];
#pragma unroll
            for (int mt = 0; mt < 2; mt++) mma_tf32(acc[mt][j], a[mt], b);
        }
    }
}

// ---------------------------------------------------------------------------
// Kernel 1: fused QKV projection.  g_x[8192,768] @ g_w[z] -> head-major q/k/v
// (tf32-rounded at write so flash can cp.async them raw).
// ---------------------------------------------------------------------------
__global__ __launch_bounds__(256, 2) void qkv_kernel() {
    extern __shared__ float smf[];
    const uint32_t su = (uint32_t)__cvta_generic_to_shared(smf);

    const float* W;
    float* outp;
    float scale;
    if (blockIdx.z == 0)      { W = g_w;           outp = g_q; scale = 0.125f; }
    else if (blockIdx.z == 1) { W = g_w + NWF;     outp = g_k; scale = 1.0f;   }
    else                      { W = g_w + 2 * NWF; outp = g_v; scale = 1.0f;   }

    const int bm = blockIdx.y * 128;
    const int bn = blockIdx.x * 128;
    const int t  = threadIdx.x;
    const int warp = t >> 5;
    const int lane = t & 31;
    const int m_base = (warp >> 1) * 32;
    const int n_base = (warp & 1) * 64;
    const int qr = lane >> 2;
    const int qc = lane & 3;

    float acc[2][8][4];
#pragma unroll
    for (int mt = 0; mt < 2; mt++)
#pragma unroll
        for (int j = 0; j < 8; j++)
#pragma unroll
            for (int e = 0; e < 4; e++) acc[mt][j][e] = 0.0f;

    gemm_fill(su, 0, 0, g_x, bm, W, bn, t);
    CP_COMMIT();

    for (int kt = 0; kt < DIM / 32; kt++) {
        if (kt + 1 < DIM / 32) {
            gemm_fill(su, (kt + 1) & 1, (kt + 1) * 32, g_x, bm, W, bn, t);
            CP_COMMIT();
            CP_WAIT1();
        } else {
            CP_WAIT0();
        }
        __syncthreads();
        gemm_compute(smf, kt & 1, m_base, n_base, qr, qc, acc);
        __syncthreads();
    }

    // Epilogue: scatter (tf32-rounded, scaled) into [b][h][n][dh]
#pragma unroll
    for (int mt = 0; mt < 2; mt++) {
#pragma unroll
        for (int j = 0; j < 8; j++) {
#pragma unroll
            for (int e = 0; e < 4; e++) {
                const int row = bm + m_base + mt * 16 + qr + (e >= 2 ? 8 : 0);
                const int col = bn + n_base + j * 8 + 2 * qc + (e & 1);
                const int bidx = row >> 11;
                const int n    = row & 2047;
                const int h    = col >> 6;
                const int dh   = col & 63;
                outp[((((size_t)bidx * NH + h) * SEQ) + n) * DH + dh] =
                    tf32r(acc[mt][j][e] * scale);
            }
        }
    }
}

// ---------------------------------------------------------------------------
// Kernel 2: flash attention, 2-stage cp.async K/V pipeline.
// 128 queries/block, 8 warps; warp w owns rows [16w,16w+16).
// smem: Ks[2][64][68], Vs[2][64][72], Ps[128][68]  = 106496 B
// ---------------------------------------------------------------------------
#define KSTRIDE 68
#define VSTRIDE 72
#define PSTRIDE 68
#define KS_STAGE (64 * KSTRIDE)            // 4352
#define VS_BASE  (2 * KS_STAGE)            // 8704
#define VS_STAGE (64 * VSTRIDE)            // 4608
#define PS_BASE  (VS_BASE + 2 * VS_STAGE)  // 17920
#define FLASH_SMEM_FLOATS (PS_BASE + 128 * PSTRIDE)  // 26624 -> 106496 B

__global__ __launch_bounds__(256, 2) void flash_kernel() {
    extern __shared__ float smf[];
    const uint32_t su = (uint32_t)__cvta_generic_to_shared(smf);
    float* Ps = smf + PS_BASE;
    const uint32_t* Psu = (const uint32_t*)Ps;

    const int qt = blockIdx.x;
    const int h  = blockIdx.y;
    const int b  = blockIdx.z;
    const int t  = threadIdx.x;
    const int warp = t >> 5;
    const int lane = t & 31;
    const int qr = lane >> 2;
    const int qc = lane & 3;
    const int wrow = warp * 16;

    const size_t head_base = ((size_t)b * NH + h) * SEQ * DH;
    const float* qbase = g_q + head_base + (size_t)qt * 128 * DH;
    const float* kbase = g_k + head_base;
    const float* vbase = g_v + head_base;

    // Prefetch K/V tile 0 (raw copy; data already tf32)
#pragma unroll
    for (int i = 0; i < 4; i++) {
        const int lin = t + i * 256;
        const int row = lin >> 4;
        const int col = (lin & 15) * 4;
        cp16(su + (uint32_t)(row * KSTRIDE + col) * 4, kbase + row * DH + col);
        cp16(su + (uint32_t)(VS_BASE + row * VSTRIDE + col) * 4, vbase + row * DH + col);
    }
    CP_COMMIT();

    // Stage Q (already tf32) into Ps, build register fragments
#pragma unroll
    for (int i = 0; i < 8; i++) {
        const int lin = (t + i * 256) * 4;
        const int row = lin >> 6;
        const int d   = lin & 63;
        *(float4*)&Ps[row * PSTRIDE + d] = *(const float4*)&qbase[lin];
    }
    __syncthreads();

    uint32_t qf[8][4];
#pragma unroll
    for (int ks = 0; ks < 8; ks++) {
        const int kk = ks * 8;
        qf[ks][0] = Psu[(wrow + qr) * PSTRIDE + kk + qc];
        qf[ks][1] = Psu[(wrow + qr + 8) * PSTRIDE + kk + qc];
        qf[ks][2] = Psu[(wrow + qr) * PSTRIDE + kk + 4 + qc];
        qf[ks][3] = Psu[(wrow + qr + 8) * PSTRIDE + kk + 4 + qc];
    }

    float o[8][4];
#pragma unroll
    for (int j = 0; j < 8; j++)
#pragma unroll
        for (int e = 0; e < 4; e++) o[j][e] = 0.0f;
    float m_lo = -INFINITY, m_hi = -INFINITY, l_lo = 0.0f, l_hi = 0.0f;

    for (int kt = 0; kt < SEQ / 64; kt++) {
        if (kt + 1 < SEQ / 64) {
            const int st = (kt + 1) & 1;
            const float* kt_base = kbase + (size_t)(kt + 1) * 64 * DH;
            const float* vt_base = vbase + (size_t)(kt + 1) * 64 * DH;
#pragma unroll
            for (int i = 0; i < 4; i++) {
                const int lin = t + i * 256;
                const int row = lin >> 4;
                const int col = (lin & 15) * 4;
                cp16(su + (uint32_t)(st * KS_STAGE + row * KSTRIDE + col) * 4,
                     kt_base + row * DH + col);
                cp16(su + (uint32_t)(VS_BASE + st * VS_STAGE + row * VSTRIDE + col) * 4,
                     vt_base + row * DH + col);
            }
            CP_COMMIT();
            CP_WAIT1();
        } else {
            CP_WAIT0();
        }
        __syncthreads();

        const uint32_t* Ksu = (const uint32_t*)(smf + (kt & 1) * KS_STAGE);
        const uint32_t* Vsu = (const uint32_t*)(smf + VS_BASE + (kt & 1) * VS_STAGE);

        // S = Q @ K^T : warp computes 16x64
        float s[8][4];
#pragma unroll
        for (int j = 0; j < 8; j++)
#pragma unroll
            for (int e = 0; e < 4; e++) s[j][e] = 0.0f;
#pragma unroll
        for (int ks = 0; ks < 8; ks++) {
            const int kk = ks * 8;
#pragma unroll
            for (int j = 0; j < 8; j++) {
                uint32_t bfr[2];
                bfr[0] = Ksu[(j * 8 + qr) * KSTRIDE + kk + qc];
                bfr[1] = Ksu[(j * 8 + qr) * KSTRIDE + kk + 4 + qc];
                mma_tf32(s[j], qf[ks], bfr);
            }
        }

        // Online softmax (quad reductions)
        float mx_lo = m_lo, mx_hi = m_hi;
#pragma unroll
        for (int j = 0; j < 8; j++) {
            mx_lo = fmaxf(mx_lo, fmaxf(s[j][0], s[j][1]));
            mx_hi = fmaxf(mx_hi, fmaxf(s[j][2], s[j][3]));
        }
        mx_lo = fmaxf(mx_lo, __shfl_xor_sync(0xffffffffu, mx_lo, 1));
        mx_lo = fmaxf(mx_lo, __shfl_xor_sync(0xffffffffu, mx_lo, 2));
        mx_hi = fmaxf(mx_hi, __shfl_xor_sync(0xffffffffu, mx_hi, 1));
        mx_hi = fmaxf(mx_hi, __shfl_xor_sync(0xffffffffu, mx_hi, 2));

        const float c_lo = __expf(m_lo - mx_lo);
        const float c_hi = __expf(m_hi - mx_hi);
        float sum_lo = 0.0f, sum_hi = 0.0f;
#pragma unroll
        for (int j = 0; j < 8; j++) {
            s[j][0] = __expf(s[j][0] - mx_lo);
            s[j][1] = __expf(s[j][1] - mx_lo);
            s[j][2] = __expf(s[j][2] - mx_hi);
            s[j][3] = __expf(s[j][3] - mx_hi);
            sum_lo += s[j][0] + s[j][1];
            sum_hi += s[j][2] + s[j][3];
        }
        sum_lo += __shfl_xor_sync(0xffffffffu, sum_lo, 1);
        sum_lo += __shfl_xor_sync(0xffffffffu, sum_lo, 2);
        sum_hi += __shfl_xor_sync(0xffffffffu, sum_hi, 1);
        sum_hi += __shfl_xor_sync(0xffffffffu, sum_hi, 2);
        l_lo = l_lo * c_lo + sum_lo;
        l_hi = l_hi * c_hi + sum_hi;
        m_lo = mx_lo;
        m_hi = mx_hi;

#pragma unroll
        for (int j = 0; j < 8; j++) {
            o[j][0] *= c_lo; o[j][1] *= c_lo;
            o[j][2] *= c_hi; o[j][3] *= c_hi;
        }

        // P (tf32-rounded) -> smem for A-fragment reuse (warp-private rows)
#pragma unroll
        for (int j = 0; j < 8; j++) {
            const int col = j * 8 + 2 * qc;
            *(float2*)&Ps[(wrow + qr) * PSTRIDE + col] =
                make_float2(tf32r(s[j][0]), tf32r(s[j][1]));
            *(float2*)&Ps[(wrow + qr + 8) * PSTRIDE + col] =
                make_float2(tf32r(s[j][2]), tf32r(s[j][3]));
        }
        __syncwarp();

        // O += P @ V
#pragma unroll
        for (int ks = 0; ks < 8; ks++) {
            const int kk = ks * 8;
            uint32_t a[4];
            a[0] = Psu[(wrow + qr) * PSTRIDE + kk + qc];
            a[1] = Psu[(wrow + qr + 8) * PSTRIDE + kk + qc];
            a[2] = Psu[(wrow + qr) * PSTRIDE + kk + 4 + qc];
            a[3] = Psu[(wrow + qr + 8) * PSTRIDE + kk + 4 + qc];
#pragma unroll
            for (int j = 0; j < 8; j++) {
                uint32_t bfr[2];
                bfr[0] = Vsu[(kk + qc) * VSTRIDE + j * 8 + qr];
                bfr[1] = Vsu[(kk + 4 + qc) * VSTRIDE + j * 8 + qr];
                mma_tf32(o[j], a, bfr);
            }
        }
        __syncthreads();   // stage (kt&1) free for refill at next iteration
    }

    // Epilogue: normalize, tf32-round, write g_att (proj cp.asyncs it raw)
    const float inv_lo = 1.0f / l_lo;
    const float inv_hi = 1.0f / l_hi;
    const int n_lo = qt * 128 + wrow + qr;
#pragma unroll
    for (int j = 0; j < 8; j++) {
        const int col = h * 64 + j * 8 + 2 * qc;
        *(float2*)&g_att[((size_t)b * SEQ + n_lo) * INNER + col] =
            make_float2(tf32r(o[j][0] * inv_lo), tf32r(o[j][1] * inv_lo));
        *(float2*)&g_att[((size_t)b * SEQ + n_lo + 8) * INNER + col] =
            make_float2(tf32r(o[j][2] * inv_hi), tf32r(o[j][3] * inv_hi));
    }
}

// ---------------------------------------------------------------------------
// Kernel 3: output projection.  out = g_att @ g_w[3] + bp  (f32 output)
// ---------------------------------------------------------------------------
__global__ __launch_bounds__(256, 2) void proj_kernel(const float* __restrict__ bp,
                                                      float* __restrict__ out) {
    extern __shared__ float smf[];
    const uint32_t su = (uint32_t)__cvta_generic_to_shared(smf);
    const float* Wp = g_w + 3 * NWF;

    const int bm = blockIdx.y * 128;
    const int bn = blockIdx.x * 128;
    const int t  = threadIdx.x;
    const int warp = t >> 5;
    const int lane = t & 31;
    const int m_base = (warp >> 1) * 32;
    const int n_base = (warp & 1) * 64;
    const int qr = lane >> 2;
    const int qc = lane & 3;

    float acc[2][8][4];
#pragma unroll
    for (int mt = 0; mt < 2; mt++)
#pragma unroll
        for (int j = 0; j < 8; j++)
#pragma unroll
            for (int e = 0; e < 4; e++) acc[mt][j][e] = 0.0f;

    gemm_fill(su, 0, 0, g_att, bm, Wp, bn, t);
    CP_COMMIT();

    for (int kt = 0; kt < INNER / 32; kt++) {
        if (kt + 1 < INNER / 32) {
            gemm_fill(su, (kt + 1) & 1, (kt + 1) * 32, g_att, bm, Wp, bn, t);
            CP_COMMIT();
            CP_WAIT1();
        } else {
            CP_WAIT0();
        }
        __syncthreads();
        gemm_compute(smf, kt & 1, m_base, n_base, qr, qc, acc);
        __syncthreads();
    }

#pragma unroll
    for (int mt = 0; mt < 2; mt++) {
#pragma unroll
        for (int j = 0; j < 8; j++) {
            const int row0 = bm + m_base + mt * 16 + qr;
            const int col0 = bn + n_base + j * 8 + 2 * qc;
            out[(size_t)row0 * DIM + col0]           = acc[mt][j][0] + bp[col0];
            out[(size_t)row0 * DIM + col0 + 1]       = acc[mt][j][1] + bp[col0 + 1];
            out[(size_t)(row0 + 8) * DIM + col0]     = acc[mt][j][2] + bp[col0];
            out[(size_t)(row0 + 8) * DIM + col0 + 1] = acc[mt][j][3] + bp[col0 + 1];
        }
    }
}

// ---------------------------------------------------------------------------
extern "C" void kernel_launch(void* const* d_in, const int* in_sizes, int n_in,
                              void* d_out, int out_size) {
    const float* x  = (const float*)d_in[0];
    const float* Wq = (const float*)d_in[1];
    const float* Wk = (const float*)d_in[2];
    const float* Wv = (const float*)d_in[3];
    const float* Wp = (const float*)d_in[4];
    const float* bp = (const float*)d_in[5];
    float* out = (float*)d_out;

    const int gemm_smem  = GEMM_SMEM_FLOATS * (int)sizeof(float);   // 71680
    const int flash_smem = FLASH_SMEM_FLOATS * (int)sizeof(float);  // 106496
    cudaFuncSetAttribute(qkv_kernel,
                         cudaFuncAttributeMaxDynamicSharedMemorySize, gemm_smem);
    cudaFuncSetAttribute(flash_kernel,
                         cudaFuncAttributeMaxDynamicSharedMemorySize, flash_smem);
    cudaFuncSetAttribute(proj_kernel,
                         cudaFuncAttributeMaxDynamicSharedMemorySize, gemm_smem);

    // 0) tf32-round x and weights into scratch
    round_kernel<<<(NXF + 4 * NWF) / 1024, 256>>>(x, Wq, Wk, Wv, Wp);

    // 1) QKV projections
    qkv_kernel<<<dim3(INNER / 128, MROWS / 128, 3), 256, gemm_smem>>>();

    // 2) flash attention
    flash_kernel<<<dim3(SEQ / 128, NH, Bb), 256, flash_smem>>>();

    // 3) output projection + bias
    proj_kernel<<<dim3(DIM / 128, MROWS / 128), 256, gemm_smem>>>(bp, out);
}

// round 7
// speedup vs baseline: 5.1943x; 1.3018x over previous
#include <cuda_runtime.h>
#include <cuda_bf16.h>
#include <math.h>
#include <stdint.h>

// Problem constants
#define Bb     4
#define SEQ    2048
#define DIM    768
#define NH     12
#define DH     64
#define INNER  768
#define MROWS  (Bb * SEQ)   // 8192
#define NXF    (MROWS * DIM)      // 6291456 floats in x
#define NWF    (DIM * INNER)      // 589824 floats per weight

// Scratch (module-static device memory; allocation-free)
__device__ float g_x[NXF];                    // tf32-rounded x
__device__ float g_w[4 * NWF];                // tf32-rounded Wq,Wk,Wv,Wp
__device__ __align__(16) __nv_bfloat16 g_qb[Bb * NH * SEQ * DH];  // [b][h][n][dh], *1/8
__device__ __align__(16) __nv_bfloat16 g_kb[Bb * NH * SEQ * DH];  // [b][h][n][dh]
__device__ __align__(16) __nv_bfloat16 g_vt[Bb * NH * DH * SEQ];  // [b][h][dh][n]
__device__ float g_att[MROWS * INNER];        // attention out (tf32), [b*n][h*64+dh]

// ---------------------------------------------------------------------------
// Helpers
// ---------------------------------------------------------------------------
__device__ __forceinline__ float tf32r(float x) {
    uint32_t u;
    asm("cvt.rna.tf32.f32 %0, %1;" : "=r"(u) : "f"(x));
    return __uint_as_float(u);
}

__device__ __forceinline__ void mma_tf32(float d[4], const uint32_t a[4],
                                         const uint32_t b[2]) {
    asm volatile(
        "mma.sync.aligned.m16n8k8.row.col.f32.tf32.tf32.f32 "
        "{%0,%1,%2,%3}, {%4,%5,%6,%7}, {%8,%9}, {%0,%1,%2,%3};"
        : "+f"(d[0]), "+f"(d[1]), "+f"(d[2]), "+f"(d[3])
        : "r"(a[0]), "r"(a[1]), "r"(a[2]), "r"(a[3]), "r"(b[0]), "r"(b[1]));
}

__device__ __forceinline__ void mma_bf16(float d[4], const uint32_t a[4],
                                         const uint32_t b[2]) {
    asm volatile(
        "mma.sync.aligned.m16n8k16.row.col.f32.bf16.bf16.f32 "
        "{%0,%1,%2,%3}, {%4,%5,%6,%7}, {%8,%9}, {%0,%1,%2,%3};"
        : "+f"(d[0]), "+f"(d[1]), "+f"(d[2]), "+f"(d[3])
        : "r"(a[0]), "r"(a[1]), "r"(a[2]), "r"(a[3]), "r"(b[0]), "r"(b[1]));
}

__device__ __forceinline__ uint32_t pack_bf16(float lo, float hi) {
    __nv_bfloat162 h = __floats2bfloat162_rn(lo, hi);
    return *(uint32_t*)&h;
}

__device__ __forceinline__ void cp16(uint32_t saddr, const void* gaddr) {
    asm volatile("cp.async.cg.shared.global [%0], [%1], 16;" :: "r"(saddr), "l"(gaddr));
}
#define CP_COMMIT()  asm volatile("cp.async.commit_group;")
#define CP_WAIT1()   asm volatile("cp.async.wait_group 1;" ::: "memory")
#define CP_WAIT0()   asm volatile("cp.async.wait_group 0;" ::: "memory")

// ---------------------------------------------------------------------------
// Kernel 0: round x and the 4 weight matrices to tf32 (elementwise, once).
// ---------------------------------------------------------------------------
__global__ void round_kernel(const float* __restrict__ x,
                             const float* __restrict__ Wq,
                             const float* __restrict__ Wk,
                             const float* __restrict__ Wv,
                             const float* __restrict__ Wp) {
    const int base = (blockIdx.x * 256 + threadIdx.x) * 4;
    if (base < NXF) {
        float4 v = *(const float4*)&x[base];
        v.x = tf32r(v.x); v.y = tf32r(v.y); v.z = tf32r(v.z); v.w = tf32r(v.w);
        *(float4*)&g_x[base] = v;
    } else {
        const int j = base - NXF;
        const int w = j / NWF;
        const int off = j - w * NWF;
        const float* src = (w == 0) ? Wq : (w == 1) ? Wk : (w == 2) ? Wv : Wp;
        float4 v = *(const float4*)&src[off];
        v.x = tf32r(v.x); v.y = tf32r(v.y); v.z = tf32r(v.z); v.w = tf32r(v.w);
        *(float4*)&g_w[w * NWF + off] = v;
    }
}

// ---------------------------------------------------------------------------
// GEMM smem geometry (qkv & proj): BM=128, BN=128, BK=32, 2-stage cp.async.
// ---------------------------------------------------------------------------
#define ASTRIDE   36
#define BSTRIDE   136
#define AS_STAGE  (128 * ASTRIDE)          // 4608 floats
#define BS_BASE   (2 * AS_STAGE)           // 9216
#define BS_STAGE  (32 * BSTRIDE)           // 4352
#define GEMM_SMEM_FLOATS (BS_BASE + 2 * BS_STAGE)   // 17920 -> 71680 B

__device__ __forceinline__ void gemm_fill(uint32_t su, int st, int k0,
                                          const float* __restrict__ gA, int bm,
                                          const float* __restrict__ gB, int bn,
                                          int t) {
#pragma unroll
    for (int i = 0; i < 4; i++) {
        const int lin = t + i * 256;
        const int row = lin >> 3;
        const int col = (lin & 7) * 4;
        cp16(su + (uint32_t)(st * AS_STAGE + row * ASTRIDE + col) * 4,
             &gA[(size_t)(bm + row) * DIM + k0 + col]);
    }
#pragma unroll
    for (int i = 0; i < 4; i++) {
        const int lin = t + i * 256;
        const int row = lin >> 5;
        const int col = (lin & 31) * 4;
        cp16(su + (uint32_t)(BS_BASE + st * BS_STAGE + row * BSTRIDE + col) * 4,
             &gB[(size_t)(k0 + row) * INNER + bn + col]);
    }
}

__device__ __forceinline__ void gemm_compute(const float* __restrict__ smf, int st,
                                             int m_base, int n_base, int qr, int qc,
                                             float acc[2][8][4]) {
    const uint32_t* A = (const uint32_t*)(smf + st * AS_STAGE);
    const uint32_t* Bm = (const uint32_t*)(smf + BS_BASE + st * BS_STAGE);
#pragma unroll
    for (int ks = 0; ks < 4; ks++) {
        const int kk = ks * 8;
        uint32_t a[2][4];
#pragma unroll
        for (int mt = 0; mt < 2; mt++) {
            const int row = m_base + mt * 16 + qr;
            a[mt][0] = A[row * ASTRIDE + kk + qc];
            a[mt][1] = A[(row + 8) * ASTRIDE + kk + qc];
            a[mt][2] = A[row * ASTRIDE + kk + 4 + qc];
            a[mt][3] = A[(row + 8) * ASTRIDE + kk + 4 + qc];
        }
#pragma unroll
        for (int j = 0; j < 8; j++) {
            uint32_t b[2];
            const int col = n_base + j * 8 + qr;
            b[0] = Bm[(kk + qc) * BSTRIDE + col];
            b[1] = Bm[(kk + 4 + qc) * BSTRIDE + col];
#pragma unroll
            for (int mt = 0; mt < 2; mt++) mma_tf32(acc[mt][j], a[mt], b);
        }
    }
}

// ---------------------------------------------------------------------------
// Kernel 1: fused QKV projection (tf32 MMA), bf16 outputs.
// z=0: q (*1/8) -> [b][h][n][dh]; z=1: k -> [b][h][n][dh]; z=2: v -> [b][h][dh][n]
// ---------------------------------------------------------------------------
__global__ __launch_bounds__(256, 2) void qkv_kernel() {
    extern __shared__ float smf[];
    const uint32_t su = (uint32_t)__cvta_generic_to_shared(smf);

    const float* W;
    __nv_bfloat16* outp;
    float scale = 1.0f;
    bool transpose = false;
    if (blockIdx.z == 0)      { W = g_w;           outp = g_qb; scale = 0.125f; }
    else if (blockIdx.z == 1) { W = g_w + NWF;     outp = g_kb; }
    else                      { W = g_w + 2 * NWF; outp = g_vt; transpose = true; }

    const int bm = blockIdx.y * 128;
    const int bn = blockIdx.x * 128;
    const int t  = threadIdx.x;
    const int warp = t >> 5;
    const int lane = t & 31;
    const int m_base = (warp >> 1) * 32;
    const int n_base = (warp & 1) * 64;
    const int qr = lane >> 2;
    const int qc = lane & 3;

    float acc[2][8][4];
#pragma unroll
    for (int mt = 0; mt < 2; mt++)
#pragma unroll
        for (int j = 0; j < 8; j++)
#pragma unroll
            for (int e = 0; e < 4; e++) acc[mt][j][e] = 0.0f;

    gemm_fill(su, 0, 0, g_x, bm, W, bn, t);
    CP_COMMIT();

    for (int kt = 0; kt < DIM / 32; kt++) {
        if (kt + 1 < DIM / 32) {
            gemm_fill(su, (kt + 1) & 1, (kt + 1) * 32, g_x, bm, W, bn, t);
            CP_COMMIT();
            CP_WAIT1();
        } else {
            CP_WAIT0();
        }
        __syncthreads();
        gemm_compute(smf, kt & 1, m_base, n_base, qr, qc, acc);
        __syncthreads();
    }

    // Epilogue: bf16 scatter into head-major (or transposed for V)
#pragma unroll
    for (int mt = 0; mt < 2; mt++) {
#pragma unroll
        for (int j = 0; j < 8; j++) {
#pragma unroll
            for (int e = 0; e < 4; e++) {
                const int row = bm + m_base + mt * 16 + qr + (e >= 2 ? 8 : 0);
                const int col = bn + n_base + j * 8 + 2 * qc + (e & 1);
                const int bidx = row >> 11;
                const int n    = row & 2047;
                const int h    = col >> 6;
                const int dh   = col & 63;
                const size_t idx = transpose
                    ? ((((size_t)bidx * NH + h) * DH) + dh) * SEQ + n
                    : ((((size_t)bidx * NH + h) * SEQ) + n) * DH + dh;
                outp[idx] = __float2bfloat16(acc[mt][j][e] * scale);
            }
        }
    }
}

// ---------------------------------------------------------------------------
// Kernel 2: flash attention, bf16 m16n8k16 MMA, 2-stage cp.async K/Vt pipeline.
// 128 queries/block, 8 warps; warp w owns rows [16w,16w+16).
// smem (u32 units): Ks[2][64][36], Vts[2][64][36], Ps[128][36] = 55296 B
// ---------------------------------------------------------------------------
#define UKSTRIDE   36
#define KS_STAGE_U (64 * UKSTRIDE)          // 2304
#define VS_BASE_U  (2 * KS_STAGE_U)         // 4608
#define PS_BASE_U  (VS_BASE_U + 2 * KS_STAGE_U)   // 9216
#define FLASH_SMEM_U (PS_BASE_U + 128 * UKSTRIDE) // 13824 -> 55296 B

__global__ __launch_bounds__(256, 2) void flash_kernel() {
    extern __shared__ uint32_t smu[];
    const uint32_t su = (uint32_t)__cvta_generic_to_shared(smu);
    uint32_t* Psu = smu + PS_BASE_U;

    const int qt = blockIdx.x;
    const int h  = blockIdx.y;
    const int b  = blockIdx.z;
    const int t  = threadIdx.x;
    const int warp = t >> 5;
    const int lane = t & 31;
    const int qr = lane >> 2;
    const int qc = lane & 3;
    const int wrow = warp * 16;

    const size_t head_nd = ((size_t)b * NH + h) * SEQ * DH;
    const __nv_bfloat16* qbase  = g_qb + head_nd + (size_t)qt * 128 * DH;
    const __nv_bfloat16* kbase  = g_kb + head_nd;
    const __nv_bfloat16* vtbase = g_vt + head_nd;   // [dh][n]

    // Prefetch K / Vt tile 0 (64 rows x 64 bf16 = 512 16B-chunks each)
#pragma unroll
    for (int i = 0; i < 2; i++) {
        const int lin = t + i * 256;           // 0..511
        const int row = lin >> 3;
        const int ch  = lin & 7;
        cp16(su + (uint32_t)(row * UKSTRIDE + ch * 4) * 4, kbase + row * DH + ch * 8);
        cp16(su + (uint32_t)(VS_BASE_U + row * UKSTRIDE + ch * 4) * 4,
             vtbase + (size_t)row * SEQ + ch * 8);
    }
    CP_COMMIT();

    // Stage Q (bf16) into Ps: 128 rows x 64 bf16 = 1024 16B-chunks (8/row)
#pragma unroll
    for (int i = 0; i < 4; i++) {
        const int lin = t + i * 256;           // 0..1023
        const int row = lin >> 3;              // 0..127
        const int ch  = lin & 7;               // 8 chunks of 8 bf16 per row
        *(float4*)&Psu[row * UKSTRIDE + ch * 4] =
            *(const float4*)&qbase[row * DH + ch * 8];
    }
    __syncthreads();

    uint32_t qf[4][4];
#pragma unroll
    for (int ks = 0; ks < 4; ks++) {
        qf[ks][0] = Psu[(wrow + qr) * UKSTRIDE + ks * 8 + qc];
        qf[ks][1] = Psu[(wrow + qr + 8) * UKSTRIDE + ks * 8 + qc];
        qf[ks][2] = Psu[(wrow + qr) * UKSTRIDE + ks * 8 + 4 + qc];
        qf[ks][3] = Psu[(wrow + qr + 8) * UKSTRIDE + ks * 8 + 4 + qc];
    }

    float o[8][4];
#pragma unroll
    for (int j = 0; j < 8; j++)
#pragma unroll
        for (int e = 0; e < 4; e++) o[j][e] = 0.0f;
    float m_lo = -INFINITY, m_hi = -INFINITY, l_lo = 0.0f, l_hi = 0.0f;

    for (int kt = 0; kt < SEQ / 64; kt++) {
        if (kt + 1 < SEQ / 64) {
            const int st = (kt + 1) & 1;
            const __nv_bfloat16* ktile = kbase + (size_t)(kt + 1) * 64 * DH;
            const __nv_bfloat16* vtile = vtbase + (size_t)(kt + 1) * 64;
#pragma unroll
            for (int i = 0; i < 2; i++) {
                const int lin = t + i * 256;
                const int row = lin >> 3;
                const int ch  = lin & 7;
                cp16(su + (uint32_t)(st * KS_STAGE_U + row * UKSTRIDE + ch * 4) * 4,
                     ktile + row * DH + ch * 8);
                cp16(su + (uint32_t)(VS_BASE_U + st * KS_STAGE_U + row * UKSTRIDE + ch * 4) * 4,
                     vtile + (size_t)row * SEQ + ch * 8);
            }
            CP_COMMIT();
            CP_WAIT1();
        } else {
            CP_WAIT0();
        }
        __syncthreads();

        const uint32_t* Ksu = smu + (kt & 1) * KS_STAGE_U;
        const uint32_t* Vsu = smu + VS_BASE_U + (kt & 1) * KS_STAGE_U;

        // S = Q @ K^T : warp computes 16x64 (4 k16-steps x 8 n-tiles)
        float s[8][4];
#pragma unroll
        for (int j = 0; j < 8; j++)
#pragma unroll
            for (int e = 0; e < 4; e++) s[j][e] = 0.0f;
#pragma unroll
        for (int ks = 0; ks < 4; ks++) {
#pragma unroll
            for (int j = 0; j < 8; j++) {
                uint32_t bfr[2];
                bfr[0] = Ksu[(j * 8 + qr) * UKSTRIDE + ks * 8 + qc];
                bfr[1] = Ksu[(j * 8 + qr) * UKSTRIDE + ks * 8 + 4 + qc];
                mma_bf16(s[j], qf[ks], bfr);
            }
        }

        // Online softmax (quad reductions; C-frag rows qr / qr+8)
        float mx_lo = m_lo, mx_hi = m_hi;
#pragma unroll
        for (int j = 0; j < 8; j++) {
            mx_lo = fmaxf(mx_lo, fmaxf(s[j][0], s[j][1]));
            mx_hi = fmaxf(mx_hi, fmaxf(s[j][2], s[j][3]));
        }
        mx_lo = fmaxf(mx_lo, __shfl_xor_sync(0xffffffffu, mx_lo, 1));
        mx_lo = fmaxf(mx_lo, __shfl_xor_sync(0xffffffffu, mx_lo, 2));
        mx_hi = fmaxf(mx_hi, __shfl_xor_sync(0xffffffffu, mx_hi, 1));
        mx_hi = fmaxf(mx_hi, __shfl_xor_sync(0xffffffffu, mx_hi, 2));

        const float c_lo = __expf(m_lo - mx_lo);
        const float c_hi = __expf(m_hi - mx_hi);
        float sum_lo = 0.0f, sum_hi = 0.0f;
#pragma unroll
        for (int j = 0; j < 8; j++) {
            s[j][0] = __expf(s[j][0] - mx_lo);
            s[j][1] = __expf(s[j][1] - mx_lo);
            s[j][2] = __expf(s[j][2] - mx_hi);
            s[j][3] = __expf(s[j][3] - mx_hi);
            sum_lo += s[j][0] + s[j][1];
            sum_hi += s[j][2] + s[j][3];
        }
        sum_lo += __shfl_xor_sync(0xffffffffu, sum_lo, 1);
        sum_lo += __shfl_xor_sync(0xffffffffu, sum_lo, 2);
        sum_hi += __shfl_xor_sync(0xffffffffu, sum_hi, 1);
        sum_hi += __shfl_xor_sync(0xffffffffu, sum_hi, 2);
        l_lo = l_lo * c_lo + sum_lo;
        l_hi = l_hi * c_hi + sum_hi;
        m_lo = mx_lo;
        m_hi = mx_hi;

#pragma unroll
        for (int j = 0; j < 8; j++) {
            o[j][0] *= c_lo; o[j][1] *= c_lo;
            o[j][2] *= c_hi; o[j][3] *= c_hi;
        }

        // P (bf16-packed) -> Ps for A-fragment reuse (warp-private rows)
#pragma unroll
        for (int j = 0; j < 8; j++) {
            Psu[(wrow + qr) * UKSTRIDE + j * 4 + qc]     = pack_bf16(s[j][0], s[j][1]);
            Psu[(wrow + qr + 8) * UKSTRIDE + j * 4 + qc] = pack_bf16(s[j][2], s[j][3]);
        }
        __syncwarp();

        // O += P @ V  (A = P rows, B: Vt smem rows are d, cols are keys)
#pragma unroll
        for (int ks = 0; ks < 4; ks++) {
            uint32_t a[4];
            a[0] = Psu[(wrow + qr) * UKSTRIDE + ks * 8 + qc];
            a[1] = Psu[(wrow + qr + 8) * UKSTRIDE + ks * 8 + qc];
            a[2] = Psu[(wrow + qr) * UKSTRIDE + ks * 8 + 4 + qc];
            a[3] = Psu[(wrow + qr + 8) * UKSTRIDE + ks * 8 + 4 + qc];
#pragma unroll
            for (int j = 0; j < 8; j++) {
                uint32_t bfr[2];
                bfr[0] = Vsu[(j * 8 + qr) * UKSTRIDE + ks * 8 + qc];
                bfr[1] = Vsu[(j * 8 + qr) * UKSTRIDE + ks * 8 + 4 + qc];
                mma_bf16(o[j], a, bfr);
            }
        }
        __syncthreads();   // stage (kt&1) free for refill at next iteration
    }

    // Epilogue: normalize, tf32-round, write g_att (proj cp.asyncs it raw)
    const float inv_lo = 1.0f / l_lo;
    const float inv_hi = 1.0f / l_hi;
    const int n_lo = qt * 128 + wrow + qr;
#pragma unroll
    for (int j = 0; j < 8; j++) {
        const int col = h * 64 + j * 8 + 2 * qc;
        *(float2*)&g_att[((size_t)b * SEQ + n_lo) * INNER + col] =
            make_float2(tf32r(o[j][0] * inv_lo), tf32r(o[j][1] * inv_lo));
        *(float2*)&g_att[((size_t)b * SEQ + n_lo + 8) * INNER + col] =
            make_float2(tf32r(o[j][2] * inv_hi), tf32r(o[j][3] * inv_hi));
    }
}

// ---------------------------------------------------------------------------
// Kernel 3: output projection (tf32).  out = g_att @ g_w[3] + bp
// ---------------------------------------------------------------------------
__global__ __launch_bounds__(256, 2) void proj_kernel(const float* __restrict__ bp,
                                                      float* __restrict__ out) {
    extern __shared__ float smf[];
    const uint32_t su = (uint32_t)__cvta_generic_to_shared(smf);
    const float* Wp = g_w + 3 * NWF;

    const int bm = blockIdx.y * 128;
    const int bn = blockIdx.x * 128;
    const int t  = threadIdx.x;
    const int warp = t >> 5;
    const int lane = t & 31;
    const int m_base = (warp >> 1) * 32;
    const int n_base = (warp & 1) * 64;
    const int qr = lane >> 2;
    const int qc = lane & 3;

    float acc[2][8][4];
#pragma unroll
    for (int mt = 0; mt < 2; mt++)
#pragma unroll
        for (int j = 0; j < 8; j++)
#pragma unroll
            for (int e = 0; e < 4; e++) acc[mt][j][e] = 0.0f;

    gemm_fill(su, 0, 0, g_att, bm, Wp, bn, t);
    CP_COMMIT();

    for (int kt = 0; kt < INNER / 32; kt++) {
        if (kt + 1 < INNER / 32) {
            gemm_fill(su, (kt + 1) & 1, (kt + 1) * 32, g_att, bm, Wp, bn, t);
            CP_COMMIT();
            CP_WAIT1();
        } else {
            CP_WAIT0();
        }
        __syncthreads();
        gemm_compute(smf, kt & 1, m_base, n_base, qr, qc, acc);
        __syncthreads();
    }

#pragma unroll
    for (int mt = 0; mt < 2; mt++) {
#pragma unroll
        for (int j = 0; j < 8; j++) {
            const int row0 = bm + m_base + mt * 16 + qr;
            const int col0 = bn + n_base + j * 8 + 2 * qc;
            out[(size_t)row0 * DIM + col0]           = acc[mt][j][0] + bp[col0];
            out[(size_t)row0 * DIM + col0 + 1]       = acc[mt][j][1] + bp[col0 + 1];
            out[(size_t)(row0 + 8) * DIM + col0]     = acc[mt][j][2] + bp[col0];
            out[(size_t)(row0 + 8) * DIM + col0 + 1] = acc[mt][j][3] + bp[col0 + 1];
        }
    }
}

// ---------------------------------------------------------------------------
extern "C" void kernel_launch(void* const* d_in, const int* in_sizes, int n_in,
                              void* d_out, int out_size) {
    const float* x  = (const float*)d_in[0];
    const float* Wq = (const float*)d_in[1];
    const float* Wk = (const float*)d_in[2];
    const float* Wv = (const float*)d_in[3];
    const float* Wp = (const float*)d_in[4];
    const float* bp = (const float*)d_in[5];
    float* out = (float*)d_out;

    const int gemm_smem  = GEMM_SMEM_FLOATS * (int)sizeof(float);   // 71680
    const int flash_smem = FLASH_SMEM_U * (int)sizeof(uint32_t);    // 55296
    cudaFuncSetAttribute(qkv_kernel,
                         cudaFuncAttributeMaxDynamicSharedMemorySize, gemm_smem);
    cudaFuncSetAttribute(flash_kernel,
                         cudaFuncAttributeMaxDynamicSharedMemorySize, flash_smem);
    cudaFuncSetAttribute(proj_kernel,
                         cudaFuncAttributeMaxDynamicSharedMemorySize, gemm_smem);

    // 0) tf32-round x and weights into scratch
    round_kernel<<<(NXF + 4 * NWF) / 1024, 256>>>(x, Wq, Wk, Wv, Wp);

    // 1) QKV projections (tf32 MMA, bf16 outputs; V transposed)
    qkv_kernel<<<dim3(INNER / 128, MROWS / 128, 3), 256, gemm_smem>>>();

    // 2) flash attention (bf16 MMA)
    flash_kernel<<<dim3(SEQ / 128, NH, Bb), 256, flash_smem>>>();

    // 3) output projection + bias (tf32 MMA)
    proj_kernel<<<dim3(DIM / 128, MROWS / 128), 256, gemm_smem>>>(bp, out);
}

// round 8
// speedup vs baseline: 5.4156x; 1.0426x over previous
#include <cuda_runtime.h>
#include <cuda_bf16.h>
#include <math.h>
#include <stdint.h>

// Problem constants
#define Bb     4
#define SEQ    2048
#define DIM    768
#define NH     12
#define DH     64
#define INNER  768
#define MROWS  (Bb * SEQ)   // 8192
#define NXF    (MROWS * DIM)      // 6291456 floats in x
#define NWF    (DIM * INNER)      // 589824 floats per weight

// Scratch (module-static device memory; allocation-free)
__device__ float g_x[NXF];                    // tf32-rounded x
__device__ float g_w[4 * NWF];                // tf32-rounded Wq,Wk,Wv,Wp
__device__ __align__(16) __nv_bfloat16 g_qb[Bb * NH * SEQ * DH];  // [b][h][n][dh], *1/8
__device__ __align__(16) __nv_bfloat16 g_kb[Bb * NH * SEQ * DH];  // [b][h][n][dh]
__device__ __align__(16) __nv_bfloat16 g_vt[Bb * NH * DH * SEQ];  // [b][h][dh][n]
__device__ float g_att[MROWS * INNER];        // attention out (tf32), [b*n][h*64+dh]

// ---------------------------------------------------------------------------
// Helpers
// ---------------------------------------------------------------------------
__device__ __forceinline__ float tf32r(float x) {
    uint32_t u;
    asm("cvt.rna.tf32.f32 %0, %1;" : "=r"(u) : "f"(x));
    return __uint_as_float(u);
}

__device__ __forceinline__ void mma_tf32(float d[4], const uint32_t a[4],
                                         const uint32_t b[2]) {
    asm volatile(
        "mma.sync.aligned.m16n8k8.row.col.f32.tf32.tf32.f32 "
        "{%0,%1,%2,%3}, {%4,%5,%6,%7}, {%8,%9}, {%0,%1,%2,%3};"
        : "+f"(d[0]), "+f"(d[1]), "+f"(d[2]), "+f"(d[3])
        : "r"(a[0]), "r"(a[1]), "r"(a[2]), "r"(a[3]), "r"(b[0]), "r"(b[1]));
}

__device__ __forceinline__ void mma_bf16(float d[4], const uint32_t a[4],
                                         const uint32_t b[2]) {
    asm volatile(
        "mma.sync.aligned.m16n8k16.row.col.f32.bf16.bf16.f32 "
        "{%0,%1,%2,%3}, {%4,%5,%6,%7}, {%8,%9}, {%0,%1,%2,%3};"
        : "+f"(d[0]), "+f"(d[1]), "+f"(d[2]), "+f"(d[3])
        : "r"(a[0]), "r"(a[1]), "r"(a[2]), "r"(a[3]), "r"(b[0]), "r"(b[1]));
}

__device__ __forceinline__ uint32_t pack_bf16(float lo, float hi) {
    __nv_bfloat162 h = __floats2bfloat162_rn(lo, hi);
    return *(uint32_t*)&h;
}

__device__ __forceinline__ void cp16(uint32_t saddr, const void* gaddr) {
    asm volatile("cp.async.cg.shared.global [%0], [%1], 16;" :: "r"(saddr), "l"(gaddr));
}
#define CP_COMMIT()  asm volatile("cp.async.commit_group;")
#define CP_WAIT1()   asm volatile("cp.async.wait_group 1;" ::: "memory")
#define CP_WAIT0()   asm volatile("cp.async.wait_group 0;" ::: "memory")

// ---------------------------------------------------------------------------
// Kernel 0: round x and the 4 weight matrices to tf32 (elementwise, once).
// ---------------------------------------------------------------------------
__global__ void round_kernel(const float* __restrict__ x,
                             const float* __restrict__ Wq,
                             const float* __restrict__ Wk,
                             const float* __restrict__ Wv,
                             const float* __restrict__ Wp) {
    const int base = (blockIdx.x * 256 + threadIdx.x) * 4;
    if (base < NXF) {
        float4 v = *(const float4*)&x[base];
        v.x = tf32r(v.x); v.y = tf32r(v.y); v.z = tf32r(v.z); v.w = tf32r(v.w);
        *(float4*)&g_x[base] = v;
    } else {
        const int j = base - NXF;
        const int w = j / NWF;
        const int off = j - w * NWF;
        const float* src = (w == 0) ? Wq : (w == 1) ? Wk : (w == 2) ? Wv : Wp;
        float4 v = *(const float4*)&src[off];
        v.x = tf32r(v.x); v.y = tf32r(v.y); v.z = tf32r(v.z); v.w = tf32r(v.w);
        *(float4*)&g_w[w * NWF + off] = v;
    }
}

// ---------------------------------------------------------------------------
// GEMM smem geometry (qkv & proj): BM=128, BN=128, BK=32, 2-stage cp.async.
// ---------------------------------------------------------------------------
#define ASTRIDE   36
#define BSTRIDE   136
#define AS_STAGE  (128 * ASTRIDE)          // 4608 floats
#define BS_BASE   (2 * AS_STAGE)           // 9216
#define BS_STAGE  (32 * BSTRIDE)           // 4352
#define GEMM_SMEM_FLOATS (BS_BASE + 2 * BS_STAGE)   // 17920 -> 71680 B

__device__ __forceinline__ void gemm_fill(uint32_t su, int st, int k0,
                                          const float* __restrict__ gA, int bm,
                                          const float* __restrict__ gB, int bn,
                                          int t) {
#pragma unroll
    for (int i = 0; i < 4; i++) {
        const int lin = t + i * 256;
        const int row = lin >> 3;
        const int col = (lin & 7) * 4;
        cp16(su + (uint32_t)(st * AS_STAGE + row * ASTRIDE + col) * 4,
             &gA[(size_t)(bm + row) * DIM + k0 + col]);
    }
#pragma unroll
    for (int i = 0; i < 4; i++) {
        const int lin = t + i * 256;
        const int row = lin >> 5;
        const int col = (lin & 31) * 4;
        cp16(su + (uint32_t)(BS_BASE + st * BS_STAGE + row * BSTRIDE + col) * 4,
             &gB[(size_t)(k0 + row) * INNER + bn + col]);
    }
}

__device__ __forceinline__ void gemm_compute(const float* __restrict__ smf, int st,
                                             int m_base, int n_base, int qr, int qc,
                                             float acc[2][8][4]) {
    const uint32_t* A = (const uint32_t*)(smf + st * AS_STAGE);
    const uint32_t* Bm = (const uint32_t*)(smf + BS_BASE + st * BS_STAGE);
#pragma unroll
    for (int ks = 0; ks < 4; ks++) {
        const int kk = ks * 8;
        uint32_t a[2][4];
#pragma unroll
        for (int mt = 0; mt < 2; mt++) {
            const int row = m_base + mt * 16 + qr;
            a[mt][0] = A[row * ASTRIDE + kk + qc];
            a[mt][1] = A[(row + 8) * ASTRIDE + kk + qc];
            a[mt][2] = A[row * ASTRIDE + kk + 4 + qc];
            a[mt][3] = A[(row + 8) * ASTRIDE + kk + 4 + qc];
        }
#pragma unroll
        for (int j = 0; j < 8; j++) {
            uint32_t b[2];
            const int col = n_base + j * 8 + qr;
            b[0] = Bm[(kk + qc) * BSTRIDE + col];
            b[1] = Bm[(kk + 4 + qc) * BSTRIDE + col];
#pragma unroll
            for (int mt = 0; mt < 2; mt++) mma_tf32(acc[mt][j], a[mt], b);
        }
    }
}

// ---------------------------------------------------------------------------
// Kernel 1: fused QKV projection (tf32 MMA), bf16 outputs.
// z=0: q (*1/8) -> [b][h][n][dh]; z=1: k -> [b][h][n][dh]; z=2: v -> [b][h][dh][n]
// ---------------------------------------------------------------------------
__global__ __launch_bounds__(256, 2) void qkv_kernel() {
    extern __shared__ float smf[];
    const uint32_t su = (uint32_t)__cvta_generic_to_shared(smf);

    const float* W;
    __nv_bfloat16* outp;
    float scale = 1.0f;
    bool transpose = false;
    if (blockIdx.z == 0)      { W = g_w;           outp = g_qb; scale = 0.125f; }
    else if (blockIdx.z == 1) { W = g_w + NWF;     outp = g_kb; }
    else                      { W = g_w + 2 * NWF; outp = g_vt; transpose = true; }

    const int bm = blockIdx.y * 128;
    const int bn = blockIdx.x * 128;
    const int t  = threadIdx.x;
    const int warp = t >> 5;
    const int lane = t & 31;
    const int m_base = (warp >> 1) * 32;
    const int n_base = (warp & 1) * 64;
    const int qr = lane >> 2;
    const int qc = lane & 3;

    float acc[2][8][4];
#pragma unroll
    for (int mt = 0; mt < 2; mt++)
#pragma unroll
        for (int j = 0; j < 8; j++)
#pragma unroll
            for (int e = 0; e < 4; e++) acc[mt][j][e] = 0.0f;

    gemm_fill(su, 0, 0, g_x, bm, W, bn, t);
    CP_COMMIT();

    for (int kt = 0; kt < DIM / 32; kt++) {
        if (kt + 1 < DIM / 32) {
            gemm_fill(su, (kt + 1) & 1, (kt + 1) * 32, g_x, bm, W, bn, t);
            CP_COMMIT();
            CP_WAIT1();
        } else {
            CP_WAIT0();
        }
        __syncthreads();
        gemm_compute(smf, kt & 1, m_base, n_base, qr, qc, acc);
        __syncthreads();
    }

    // Epilogue: bf16 scatter into head-major (or transposed for V)
#pragma unroll
    for (int mt = 0; mt < 2; mt++) {
#pragma unroll
        for (int j = 0; j < 8; j++) {
#pragma unroll
            for (int e = 0; e < 4; e++) {
                const int row = bm + m_base + mt * 16 + qr + (e >= 2 ? 8 : 0);
                const int col = bn + n_base + j * 8 + 2 * qc + (e & 1);
                const int bidx = row >> 11;
                const int n    = row & 2047;
                const int h    = col >> 6;
                const int dh   = col & 63;
                const size_t idx = transpose
                    ? ((((size_t)bidx * NH + h) * DH) + dh) * SEQ + n
                    : ((((size_t)bidx * NH + h) * SEQ) + n) * DH + dh;
                outp[idx] = __float2bfloat16(acc[mt][j][e] * scale);
            }
        }
    }
}

// ---------------------------------------------------------------------------
// Kernel 2: flash attention, bf16 m16n8k16 MMA, 2-stage cp.async K/Vt pipeline.
// 128 queries/block, 8 warps; warp w owns rows [16w,16w+16).
// P never touches smem: S C-fragments ARE the PV A-fragments (bf16-packed).
// smem (u32 units): Ks[2][64][36], Vts[2][64][36], Ps[128][36] (Q staging only)
// ---------------------------------------------------------------------------
#define UKSTRIDE   36
#define KS_STAGE_U (64 * UKSTRIDE)          // 2304
#define VS_BASE_U  (2 * KS_STAGE_U)         // 4608
#define PS_BASE_U  (VS_BASE_U + 2 * KS_STAGE_U)   // 9216
#define FLASH_SMEM_U (PS_BASE_U + 128 * UKSTRIDE) // 13824 -> 55296 B

__global__ __launch_bounds__(256, 2) void flash_kernel() {
    extern __shared__ uint32_t smu[];
    const uint32_t su = (uint32_t)__cvta_generic_to_shared(smu);
    uint32_t* Psu = smu + PS_BASE_U;

    const int qt = blockIdx.x;
    const int h  = blockIdx.y;
    const int b  = blockIdx.z;
    const int t  = threadIdx.x;
    const int warp = t >> 5;
    const int lane = t & 31;
    const int qr = lane >> 2;
    const int qc = lane & 3;
    const int wrow = warp * 16;

    const size_t head_nd = ((size_t)b * NH + h) * SEQ * DH;
    const __nv_bfloat16* qbase  = g_qb + head_nd + (size_t)qt * 128 * DH;
    const __nv_bfloat16* kbase  = g_kb + head_nd;
    const __nv_bfloat16* vtbase = g_vt + head_nd;   // [dh][n]

    // Prefetch K / Vt tile 0 (64 rows x 64 bf16 = 512 16B-chunks each)
#pragma unroll
    for (int i = 0; i < 2; i++) {
        const int lin = t + i * 256;           // 0..511
        const int row = lin >> 3;
        const int ch  = lin & 7;
        cp16(su + (uint32_t)(row * UKSTRIDE + ch * 4) * 4, kbase + row * DH + ch * 8);
        cp16(su + (uint32_t)(VS_BASE_U + row * UKSTRIDE + ch * 4) * 4,
             vtbase + (size_t)row * SEQ + ch * 8);
    }
    CP_COMMIT();

    // Stage Q (bf16) into Ps: 128 rows x 64 bf16 = 1024 16B-chunks (8/row)
#pragma unroll
    for (int i = 0; i < 4; i++) {
        const int lin = t + i * 256;           // 0..1023
        const int row = lin >> 3;              // 0..127
        const int ch  = lin & 7;               // 8 chunks of 8 bf16 per row
        *(float4*)&Psu[row * UKSTRIDE + ch * 4] =
            *(const float4*)&qbase[row * DH + ch * 8];
    }
    __syncthreads();

    uint32_t qf[4][4];
#pragma unroll
    for (int ks = 0; ks < 4; ks++) {
        qf[ks][0] = Psu[(wrow + qr) * UKSTRIDE + ks * 8 + qc];
        qf[ks][1] = Psu[(wrow + qr + 8) * UKSTRIDE + ks * 8 + qc];
        qf[ks][2] = Psu[(wrow + qr) * UKSTRIDE + ks * 8 + 4 + qc];
        qf[ks][3] = Psu[(wrow + qr + 8) * UKSTRIDE + ks * 8 + 4 + qc];
    }

    float o[8][4];
#pragma unroll
    for (int j = 0; j < 8; j++)
#pragma unroll
        for (int e = 0; e < 4; e++) o[j][e] = 0.0f;
    float m_lo = -INFINITY, m_hi = -INFINITY, l_lo = 0.0f, l_hi = 0.0f;

    for (int kt = 0; kt < SEQ / 64; kt++) {
        if (kt + 1 < SEQ / 64) {
            const int st = (kt + 1) & 1;
            const __nv_bfloat16* ktile = kbase + (size_t)(kt + 1) * 64 * DH;
            const __nv_bfloat16* vtile = vtbase + (size_t)(kt + 1) * 64;
#pragma unroll
            for (int i = 0; i < 2; i++) {
                const int lin = t + i * 256;
                const int row = lin >> 3;
                const int ch  = lin & 7;
                cp16(su + (uint32_t)(st * KS_STAGE_U + row * UKSTRIDE + ch * 4) * 4,
                     ktile + row * DH + ch * 8);
                cp16(su + (uint32_t)(VS_BASE_U + st * KS_STAGE_U + row * UKSTRIDE + ch * 4) * 4,
                     vtile + (size_t)row * SEQ + ch * 8);
            }
            CP_COMMIT();
            CP_WAIT1();
        } else {
            CP_WAIT0();
        }
        __syncthreads();

        const uint32_t* Ksu = smu + (kt & 1) * KS_STAGE_U;
        const uint32_t* Vsu = smu + VS_BASE_U + (kt & 1) * KS_STAGE_U;

        // S = Q @ K^T : warp computes 16x64 (4 k16-steps x 8 n-tiles)
        float s[8][4];
#pragma unroll
        for (int j = 0; j < 8; j++)
#pragma unroll
            for (int e = 0; e < 4; e++) s[j][e] = 0.0f;
#pragma unroll
        for (int ks = 0; ks < 4; ks++) {
#pragma unroll
            for (int j = 0; j < 8; j++) {
                uint32_t bfr[2];
                bfr[0] = Ksu[(j * 8 + qr) * UKSTRIDE + ks * 8 + qc];
                bfr[1] = Ksu[(j * 8 + qr) * UKSTRIDE + ks * 8 + 4 + qc];
                mma_bf16(s[j], qf[ks], bfr);
            }
        }

        // Online softmax (quad reductions; C-frag rows qr / qr+8)
        float mx_lo = m_lo, mx_hi = m_hi;
#pragma unroll
        for (int j = 0; j < 8; j++) {
            mx_lo = fmaxf(mx_lo, fmaxf(s[j][0], s[j][1]));
            mx_hi = fmaxf(mx_hi, fmaxf(s[j][2], s[j][3]));
        }
        mx_lo = fmaxf(mx_lo, __shfl_xor_sync(0xffffffffu, mx_lo, 1));
        mx_lo = fmaxf(mx_lo, __shfl_xor_sync(0xffffffffu, mx_lo, 2));
        mx_hi = fmaxf(mx_hi, __shfl_xor_sync(0xffffffffu, mx_hi, 1));
        mx_hi = fmaxf(mx_hi, __shfl_xor_sync(0xffffffffu, mx_hi, 2));

        const float c_lo = __expf(m_lo - mx_lo);
        const float c_hi = __expf(m_hi - mx_hi);
        float sum_lo = 0.0f, sum_hi = 0.0f;
#pragma unroll
        for (int j = 0; j < 8; j++) {
            s[j][0] = __expf(s[j][0] - mx_lo);
            s[j][1] = __expf(s[j][1] - mx_lo);
            s[j][2] = __expf(s[j][2] - mx_hi);
            s[j][3] = __expf(s[j][3] - mx_hi);
            sum_lo += s[j][0] + s[j][1];
            sum_hi += s[j][2] + s[j][3];
        }
        sum_lo += __shfl_xor_sync(0xffffffffu, sum_lo, 1);
        sum_lo += __shfl_xor_sync(0xffffffffu, sum_lo, 2);
        sum_hi += __shfl_xor_sync(0xffffffffu, sum_hi, 1);
        sum_hi += __shfl_xor_sync(0xffffffffu, sum_hi, 2);
        l_lo = l_lo * c_lo + sum_lo;
        l_hi = l_hi * c_hi + sum_hi;
        m_lo = mx_lo;
        m_hi = mx_hi;

#pragma unroll
        for (int j = 0; j < 8; j++) {
            o[j][0] *= c_lo; o[j][1] *= c_lo;
            o[j][2] *= c_hi; o[j][3] *= c_hi;
        }

        // O += P @ V : A-frags come DIRECTLY from S C-frags (no smem round-trip).
        // k16-block ks covers keys 16ks..16ks+15 = n-tiles 2ks (keys +0..7) and
        // 2ks+1 (keys +8..15):
        //   a0 = (row qr,   keys 16ks+2qc,+1) = s[2ks][0..1]
        //   a1 = (row qr+8, same keys)        = s[2ks][2..3]
        //   a2 = (row qr,   keys +8)          = s[2ks+1][0..1]
        //   a3 = (row qr+8, keys +8)          = s[2ks+1][2..3]
#pragma unroll
        for (int ks = 0; ks < 4; ks++) {
            uint32_t a[4];
            a[0] = pack_bf16(s[2 * ks][0],     s[2 * ks][1]);
            a[1] = pack_bf16(s[2 * ks][2],     s[2 * ks][3]);
            a[2] = pack_bf16(s[2 * ks + 1][0], s[2 * ks + 1][1]);
            a[3] = pack_bf16(s[2 * ks + 1][2], s[2 * ks + 1][3]);
#pragma unroll
            for (int j = 0; j < 8; j++) {
                uint32_t bfr[2];
                bfr[0] = Vsu[(j * 8 + qr) * UKSTRIDE + ks * 8 + qc];
                bfr[1] = Vsu[(j * 8 + qr) * UKSTRIDE + ks * 8 + 4 + qc];
                mma_bf16(o[j], a, bfr);
            }
        }
        __syncthreads();   // stage (kt&1) free for refill at next iteration
    }

    // Epilogue: normalize, tf32-round, write g_att (proj cp.asyncs it raw)
    const float inv_lo = 1.0f / l_lo;
    const float inv_hi = 1.0f / l_hi;
    const int n_lo = qt * 128 + wrow + qr;
#pragma unroll
    for (int j = 0; j < 8; j++) {
        const int col = h * 64 + j * 8 + 2 * qc;
        *(float2*)&g_att[((size_t)b * SEQ + n_lo) * INNER + col] =
            make_float2(tf32r(o[j][0] * inv_lo), tf32r(o[j][1] * inv_lo));
        *(float2*)&g_att[((size_t)b * SEQ + n_lo + 8) * INNER + col] =
            make_float2(tf32r(o[j][2] * inv_hi), tf32r(o[j][3] * inv_hi));
    }
}

// ---------------------------------------------------------------------------
// Kernel 3: output projection (tf32).  out = g_att @ g_w[3] + bp
// ---------------------------------------------------------------------------
__global__ __launch_bounds__(256, 2) void proj_kernel(const float* __restrict__ bp,
                                                      float* __restrict__ out) {
    extern __shared__ float smf[];
    const uint32_t su = (uint32_t)__cvta_generic_to_shared(smf);
    const float* Wp = g_w + 3 * NWF;

    const int bm = blockIdx.y * 128;
    const int bn = blockIdx.x * 128;
    const int t  = threadIdx.x;
    const int warp = t >> 5;
    const int lane = t & 31;
    const int m_base = (warp >> 1) * 32;
    const int n_base = (warp & 1) * 64;
    const int qr = lane >> 2;
    const int qc = lane & 3;

    float acc[2][8][4];
#pragma unroll
    for (int mt = 0; mt < 2; mt++)
#pragma unroll
        for (int j = 0; j < 8; j++)
#pragma unroll
            for (int e = 0; e < 4; e++) acc[mt][j][e] = 0.0f;

    gemm_fill(su, 0, 0, g_att, bm, Wp, bn, t);
    CP_COMMIT();

    for (int kt = 0; kt < INNER / 32; kt++) {
        if (kt + 1 < INNER / 32) {
            gemm_fill(su, (kt + 1) & 1, (kt + 1) * 32, g_att, bm, Wp, bn, t);
            CP_COMMIT();
            CP_WAIT1();
        } else {
            CP_WAIT0();
        }
        __syncthreads();
        gemm_compute(smf, kt & 1, m_base, n_base, qr, qc, acc);
        __syncthreads();
    }

#pragma unroll
    for (int mt = 0; mt < 2; mt++) {
#pragma unroll
        for (int j = 0; j < 8; j++) {
            const int row0 = bm + m_base + mt * 16 + qr;
            const int col0 = bn + n_base + j * 8 + 2 * qc;
            out[(size_t)row0 * DIM + col0]           = acc[mt][j][0] + bp[col0];
            out[(size_t)row0 * DIM + col0 + 1]       = acc[mt][j][1] + bp[col0 + 1];
            out[(size_t)(row0 + 8) * DIM + col0]     = acc[mt][j][2] + bp[col0];
            out[(size_t)(row0 + 8) * DIM + col0 + 1] = acc[mt][j][3] + bp[col0 + 1];
        }
    }
}

// ---------------------------------------------------------------------------
extern "C" void kernel_launch(void* const* d_in, const int* in_sizes, int n_in,
                              void* d_out, int out_size) {
    const float* x  = (const float*)d_in[0];
    const float* Wq = (const float*)d_in[1];
    const float* Wk = (const float*)d_in[2];
    const float* Wv = (const float*)d_in[3];
    const float* Wp = (const float*)d_in[4];
    const float* bp = (const float*)d_in[5];
    float* out = (float*)d_out;

    const int gemm_smem  = GEMM_SMEM_FLOATS * (int)sizeof(float);   // 71680
    const int flash_smem = FLASH_SMEM_U * (int)sizeof(uint32_t);    // 55296
    cudaFuncSetAttribute(qkv_kernel,
                         cudaFuncAttributeMaxDynamicSharedMemorySize, gemm_smem);
    cudaFuncSetAttribute(flash_kernel,
                         cudaFuncAttributeMaxDynamicSharedMemorySize, flash_smem);
    cudaFuncSetAttribute(proj_kernel,
                         cudaFuncAttributeMaxDynamicSharedMemorySize, gemm_smem);

    // 0) tf32-round x and weights into scratch
    round_kernel<<<(NXF + 4 * NWF) / 1024, 256>>>(x, Wq, Wk, Wv, Wp);

    // 1) QKV projections (tf32 MMA, bf16 outputs; V transposed)
    qkv_kernel<<<dim3(INNER / 128, MROWS / 128, 3), 256, gemm_smem>>>();

    // 2) flash attention (bf16 MMA, register-resident P)
    flash_kernel<<<dim3(SEQ / 128, NH, Bb), 256, flash_smem>>>();

    // 3) output projection + bias (tf32 MMA)
    proj_kernel<<<dim3(DIM / 128, MROWS / 128), 256, gemm_smem>>>(bp, out);
}

// round 10
// speedup vs baseline: 5.4745x; 1.0109x over previous
#include <cuda_runtime.h>
#include <cuda_bf16.h>
#include <math.h>
#include <stdint.h>

// Problem constants
#define Bb     4
#define SEQ    2048
#define DIM    768
#define NH     12
#define DH     64
#define INNER  768
#define MROWS  (Bb * SEQ)   // 8192
#define NXF    (MROWS * DIM)      // 6291456 floats in x
#define NWF    (DIM * INNER)      // 589824 floats per weight

// Scratch (module-static device memory; allocation-free)
__device__ float g_x[NXF];                    // tf32-rounded x
__device__ float g_w[4 * NWF];                // tf32-rounded Wq,Wk,Wv,Wp
__device__ __align__(16) __nv_bfloat16 g_qb[Bb * NH * SEQ * DH];  // [b][h][n][dh], *1/8
__device__ __align__(16) __nv_bfloat16 g_kb[Bb * NH * SEQ * DH];  // [b][h][n][dh]
__device__ __align__(16) __nv_bfloat16 g_vt[Bb * NH * DH * SEQ];  // [b][h][dh][n]
__device__ float g_att[MROWS * INNER];        // attention out (tf32), [b*n][h*64+dh]

// ---------------------------------------------------------------------------
// Helpers
// ---------------------------------------------------------------------------
__device__ __forceinline__ float tf32r(float x) {
    uint32_t u;
    asm("cvt.rna.tf32.f32 %0, %1;" : "=r"(u) : "f"(x));
    return __uint_as_float(u);
}

__device__ __forceinline__ void mma_tf32(float d[4], const uint32_t a[4],
                                         const uint32_t b[2]) {
    asm volatile(
        "mma.sync.aligned.m16n8k8.row.col.f32.tf32.tf32.f32 "
        "{%0,%1,%2,%3}, {%4,%5,%6,%7}, {%8,%9}, {%0,%1,%2,%3};"
        : "+f"(d[0]), "+f"(d[1]), "+f"(d[2]), "+f"(d[3])
        : "r"(a[0]), "r"(a[1]), "r"(a[2]), "r"(a[3]), "r"(b[0]), "r"(b[1]));
}

__device__ __forceinline__ void mma_bf16(float d[4], const uint32_t a[4],
                                         const uint32_t b[2]) {
    asm volatile(
        "mma.sync.aligned.m16n8k16.row.col.f32.bf16.bf16.f32 "
        "{%0,%1,%2,%3}, {%4,%5,%6,%7}, {%8,%9}, {%0,%1,%2,%3};"
        : "+f"(d[0]), "+f"(d[1]), "+f"(d[2]), "+f"(d[3])
        : "r"(a[0]), "r"(a[1]), "r"(a[2]), "r"(a[3]), "r"(b[0]), "r"(b[1]));
}

// Warp-collective: load 4 8x8 b16 matrices; lanes 0-7/8-15/16-23/24-31 supply
// the row addresses of matrices 0/1/2/3.
__device__ __forceinline__ void ldmatrix_x4(uint32_t& r0, uint32_t& r1,
                                            uint32_t& r2, uint32_t& r3,
                                            uint32_t saddr) {
    asm volatile(
        "ldmatrix.sync.aligned.m8n8.x4.shared.b16 {%0,%1,%2,%3}, [%4];"
        : "=r"(r0), "=r"(r1), "=r"(r2), "=r"(r3) : "r"(saddr));
}

__device__ __forceinline__ uint32_t pack_bf16(float lo, float hi) {
    __nv_bfloat162 h = __floats2bfloat162_rn(lo, hi);
    return *(uint32_t*)&h;
}

__device__ __forceinline__ void cp16(uint32_t saddr, const void* gaddr) {
    asm volatile("cp.async.cg.shared.global [%0], [%1], 16;" :: "r"(saddr), "l"(gaddr));
}
#define CP_COMMIT()  asm volatile("cp.async.commit_group;")
#define CP_WAIT1()   asm volatile("cp.async.wait_group 1;" ::: "memory")
#define CP_WAIT0()   asm volatile("cp.async.wait_group 0;" ::: "memory")

// ---------------------------------------------------------------------------
// Kernel 0: round x and the 4 weight matrices to tf32 (elementwise, once).
// ---------------------------------------------------------------------------
__global__ void round_kernel(const float* __restrict__ x,
                             const float* __restrict__ Wq,
                             const float* __restrict__ Wk,
                             const float* __restrict__ Wv,
                             const float* __restrict__ Wp) {
    const int base = (blockIdx.x * 256 + threadIdx.x) * 4;
    if (base < NXF) {
        float4 v = *(const float4*)&x[base];
        v.x = tf32r(v.x); v.y = tf32r(v.y); v.z = tf32r(v.z); v.w = tf32r(v.w);
        *(float4*)&g_x[base] = v;
    } else {
        const int j = base - NXF;
        const int w = j / NWF;
        const int off = j - w * NWF;
        const float* src = (w == 0) ? Wq : (w == 1) ? Wk : (w == 2) ? Wv : Wp;
        float4 v = *(const float4*)&src[off];
        v.x = tf32r(v.x); v.y = tf32r(v.y); v.z = tf32r(v.z); v.w = tf32r(v.w);
        *(float4*)&g_w[w * NWF + off] = v;
    }
}

// ---------------------------------------------------------------------------
// GEMM smem geometry (qkv & proj): BM=128, BN=128, BK=32, 2-stage cp.async.
// ---------------------------------------------------------------------------
#define ASTRIDE   36
#define BSTRIDE   136
#define AS_STAGE  (128 * ASTRIDE)          // 4608 floats
#define BS_BASE   (2 * AS_STAGE)           // 9216
#define BS_STAGE  (32 * BSTRIDE)           // 4352
#define GEMM_SMEM_FLOATS (BS_BASE + 2 * BS_STAGE)   // 17920 -> 71680 B

__device__ __forceinline__ void gemm_fill(uint32_t su, int st, int k0,
                                          const float* __restrict__ gA, int bm,
                                          const float* __restrict__ gB, int bn,
                                          int t) {
#pragma unroll
    for (int i = 0; i < 4; i++) {
        const int lin = t + i * 256;
        const int row = lin >> 3;
        const int col = (lin & 7) * 4;
        cp16(su + (uint32_t)(st * AS_STAGE + row * ASTRIDE + col) * 4,
             &gA[(size_t)(bm + row) * DIM + k0 + col]);
    }
#pragma unroll
    for (int i = 0; i < 4; i++) {
        const int lin = t + i * 256;
        const int row = lin >> 5;
        const int col = (lin & 31) * 4;
        cp16(su + (uint32_t)(BS_BASE + st * BS_STAGE + row * BSTRIDE + col) * 4,
             &gB[(size_t)(k0 + row) * INNER + bn + col]);
    }
}

__device__ __forceinline__ void gemm_compute(const float* __restrict__ smf, int st,
                                             int m_base, int n_base, int qr, int qc,
                                             float acc[2][8][4]) {
    const uint32_t* A = (const uint32_t*)(smf + st * AS_STAGE);
    const uint32_t* Bm = (const uint32_t*)(smf + BS_BASE + st * BS_STAGE);
#pragma unroll
    for (int ks = 0; ks < 4; ks++) {
        const int kk = ks * 8;
        uint32_t a[2][4];
#pragma unroll
        for (int mt = 0; mt < 2; mt++) {
            const int row = m_base + mt * 16 + qr;
            a[mt][0] = A[row * ASTRIDE + kk + qc];
            a[mt][1] = A[(row + 8) * ASTRIDE + kk + qc];
            a[mt][2] = A[row * ASTRIDE + kk + 4 + qc];
            a[mt][3] = A[(row + 8) * ASTRIDE + kk + 4 + qc];
        }
#pragma unroll
        for (int j = 0; j < 8; j++) {
            uint32_t b[2];
            const int col = n_base + j * 8 + qr;
            b[0] = Bm[(kk + qc) * BSTRIDE + col];
            b[1] = Bm[(kk + 4 + qc) * BSTRIDE + col];
#pragma unroll
            for (int mt = 0; mt < 2; mt++) mma_tf32(acc[mt][j], a[mt], b);
        }
    }
}

// ---------------------------------------------------------------------------
// Kernel 1: fused QKV projection (tf32 MMA), bf16 outputs.
// z=0: q (*1/8) -> [b][h][n][dh]; z=1: k -> [b][h][n][dh]; z=2: v -> [b][h][dh][n]
// ---------------------------------------------------------------------------
__global__ __launch_bounds__(256, 2) void qkv_kernel() {
    extern __shared__ float smf[];
    const uint32_t su = (uint32_t)__cvta_generic_to_shared(smf);

    const float* W;
    __nv_bfloat16* outp;
    float scale = 1.0f;
    bool transpose = false;
    if (blockIdx.z == 0)      { W = g_w;           outp = g_qb; scale = 0.125f; }
    else if (blockIdx.z == 1) { W = g_w + NWF;     outp = g_kb; }
    else                      { W = g_w + 2 * NWF; outp = g_vt; transpose = true; }

    const int bm = blockIdx.y * 128;
    const int bn = blockIdx.x * 128;
    const int t  = threadIdx.x;
    const int warp = t >> 5;
    const int lane = t & 31;
    const int m_base = (warp >> 1) * 32;
    const int n_base = (warp & 1) * 64;
    const int qr = lane >> 2;
    const int qc = lane & 3;

    float acc[2][8][4];
#pragma unroll
    for (int mt = 0; mt < 2; mt++)
#pragma unroll
        for (int j = 0; j < 8; j++)
#pragma unroll
            for (int e = 0; e < 4; e++) acc[mt][j][e] = 0.0f;

    gemm_fill(su, 0, 0, g_x, bm, W, bn, t);
    CP_COMMIT();

    for (int kt = 0; kt < DIM / 32; kt++) {
        if (kt + 1 < DIM / 32) {
            gemm_fill(su, (kt + 1) & 1, (kt + 1) * 32, g_x, bm, W, bn, t);
            CP_COMMIT();
            CP_WAIT1();
        } else {
            CP_WAIT0();
        }
        __syncthreads();
        gemm_compute(smf, kt & 1, m_base, n_base, qr, qc, acc);
        __syncthreads();
    }

    // Epilogue: bf16 scatter into head-major (or transposed for V)
#pragma unroll
    for (int mt = 0; mt < 2; mt++) {
#pragma unroll
        for (int j = 0; j < 8; j++) {
#pragma unroll
            for (int e = 0; e < 4; e++) {
                const int row = bm + m_base + mt * 16 + qr + (e >= 2 ? 8 : 0);
                const int col = bn + n_base + j * 8 + 2 * qc + (e & 1);
                const int bidx = row >> 11;
                const int n    = row & 2047;
                const int h    = col >> 6;
                const int dh   = col & 63;
                const size_t idx = transpose
                    ? ((((size_t)bidx * NH + h) * DH) + dh) * SEQ + n
                    : ((((size_t)bidx * NH + h) * SEQ) + n) * DH + dh;
                outp[idx] = __float2bfloat16(acc[mt][j][e] * scale);
            }
        }
    }
}

// ---------------------------------------------------------------------------
// Kernel 2: flash attention, bf16 m16n8k16 MMA, 2-stage cp.async K/Vt pipeline.
// 128 queries/block, 8 warps; warp w owns rows [16w,16w+16).
// B-fragments loaded via ldmatrix.x4 (2 n-tiles per instruction).
// P never touches smem: S C-frags ARE the PV A-frags (bf16-packed).
// ---------------------------------------------------------------------------
#define UKSTRIDE   36
#define KS_STAGE_U (64 * UKSTRIDE)          // 2304
#define VS_BASE_U  (2 * KS_STAGE_U)         // 4608
#define PS_BASE_U  (VS_BASE_U + 2 * KS_STAGE_U)   // 9216
#define FLASH_SMEM_U (PS_BASE_U + 128 * UKSTRIDE) // 13824 -> 55296 B

__global__ __launch_bounds__(256, 2) void flash_kernel() {
    extern __shared__ uint32_t smu[];
    const uint32_t su = (uint32_t)__cvta_generic_to_shared(smu);
    uint32_t* Psu = smu + PS_BASE_U;

    const int qt = blockIdx.x;
    const int h  = blockIdx.y;
    const int b  = blockIdx.z;
    const int t  = threadIdx.x;
    const int warp = t >> 5;
    const int lane = t & 31;
    const int qr = lane >> 2;
    const int qc = lane & 3;
    const int wrow = warp * 16;

    // ldmatrix lane base: matrices 0/1 = n-tile 2jp (k-halves 0/+4),
    // matrices 2/3 = n-tile 2jp+1. Lane l: row (l&7) + (l>=16 ? 8 : 0) within
    // the jp pair, col half +4 u32 if bit3.
    const int lm_row = (lane & 7) + ((lane & 16) >> 1);
    const int lm_col = (lane & 8) >> 1;
    const uint32_t lm_off = (uint32_t)(lm_row * UKSTRIDE + lm_col) * 4;

    const size_t head_nd = ((size_t)b * NH + h) * SEQ * DH;
    const __nv_bfloat16* qbase  = g_qb + head_nd + (size_t)qt * 128 * DH;
    const __nv_bfloat16* kbase  = g_kb + head_nd;
    const __nv_bfloat16* vtbase = g_vt + head_nd;   // [dh][n]

    // Prefetch K / Vt tile 0 (64 rows x 64 bf16 = 512 16B-chunks each)
#pragma unroll
    for (int i = 0; i < 2; i++) {
        const int lin = t + i * 256;           // 0..511
        const int row = lin >> 3;
        const int ch  = lin & 7;
        cp16(su + (uint32_t)(row * UKSTRIDE + ch * 4) * 4, kbase + row * DH + ch * 8);
        cp16(su + (uint32_t)(VS_BASE_U + row * UKSTRIDE + ch * 4) * 4,
             vtbase + (size_t)row * SEQ + ch * 8);
    }
    CP_COMMIT();

    // Stage Q (bf16) into Ps: 128 rows x 64 bf16 = 1024 16B-chunks (8/row)
#pragma unroll
    for (int i = 0; i < 4; i++) {
        const int lin = t + i * 256;           // 0..1023
        const int row = lin >> 3;              // 0..127
        const int ch  = lin & 7;               // 8 chunks of 8 bf16 per row
        *(float4*)&Psu[row * UKSTRIDE + ch * 4] =
            *(const float4*)&qbase[row * DH + ch * 8];
    }
    __syncthreads();

    uint32_t qf[4][4];
#pragma unroll
    for (int ks = 0; ks < 4; ks++) {
        qf[ks][0] = Psu[(wrow + qr) * UKSTRIDE + ks * 8 + qc];
        qf[ks][1] = Psu[(wrow + qr + 8) * UKSTRIDE + ks * 8 + qc];
        qf[ks][2] = Psu[(wrow + qr) * UKSTRIDE + ks * 8 + 4 + qc];
        qf[ks][3] = Psu[(wrow + qr + 8) * UKSTRIDE + ks * 8 + 4 + qc];
    }

    float o[8][4];
#pragma unroll
    for (int j = 0; j < 8; j++)
#pragma unroll
        for (int e = 0; e < 4; e++) o[j][e] = 0.0f;
    float m_lo = -INFINITY, m_hi = -INFINITY, l_lo = 0.0f, l_hi = 0.0f;

    for (int kt = 0; kt < SEQ / 64; kt++) {
        if (kt + 1 < SEQ / 64) {
            const int st = (kt + 1) & 1;
            const __nv_bfloat16* ktile = kbase + (size_t)(kt + 1) * 64 * DH;
            const __nv_bfloat16* vtile = vtbase + (size_t)(kt + 1) * 64;
#pragma unroll
            for (int i = 0; i < 2; i++) {
                const int lin = t + i * 256;
                const int row = lin >> 3;
                const int ch  = lin & 7;
                cp16(su + (uint32_t)(st * KS_STAGE_U + row * UKSTRIDE + ch * 4) * 4,
                     ktile + row * DH + ch * 8);
                cp16(su + (uint32_t)(VS_BASE_U + st * KS_STAGE_U + row * UKSTRIDE + ch * 4) * 4,
                     vtile + (size_t)row * SEQ + ch * 8);
            }
            CP_COMMIT();
            CP_WAIT1();
        } else {
            CP_WAIT0();
        }
        __syncthreads();

        const uint32_t k_lm = su + (uint32_t)((kt & 1) * KS_STAGE_U) * 4 + lm_off;
        const uint32_t v_lm = su + (uint32_t)(VS_BASE_U + (kt & 1) * KS_STAGE_U) * 4 + lm_off;

        // S = Q @ K^T : warp computes 16x64; B-frags via ldmatrix.x4
        float s[8][4];
#pragma unroll
        for (int j = 0; j < 8; j++)
#pragma unroll
            for (int e = 0; e < 4; e++) s[j][e] = 0.0f;
#pragma unroll
        for (int ks = 0; ks < 4; ks++) {
#pragma unroll
            for (int jp = 0; jp < 4; jp++) {
                uint32_t b0, b1, b2, b3;
                ldmatrix_x4(b0, b1, b2, b3,
                            k_lm + (uint32_t)(jp * 16 * UKSTRIDE + ks * 8) * 4);
                uint32_t br0[2] = {b0, b1};
                uint32_t br1[2] = {b2, b3};
                mma_bf16(s[2 * jp],     qf[ks], br0);
                mma_bf16(s[2 * jp + 1], qf[ks], br1);
            }
        }

        // Online softmax (quad reductions; C-frag rows qr / qr+8)
        float mx_lo = m_lo, mx_hi = m_hi;
#pragma unroll
        for (int j = 0; j < 8; j++) {
            mx_lo = fmaxf(mx_lo, fmaxf(s[j][0], s[j][1]));
            mx_hi = fmaxf(mx_hi, fmaxf(s[j][2], s[j][3]));
        }
        mx_lo = fmaxf(mx_lo, __shfl_xor_sync(0xffffffffu, mx_lo, 1));
        mx_lo = fmaxf(mx_lo, __shfl_xor_sync(0xffffffffu, mx_lo, 2));
        mx_hi = fmaxf(mx_hi, __shfl_xor_sync(0xffffffffu, mx_hi, 1));
        mx_hi = fmaxf(mx_hi, __shfl_xor_sync(0xffffffffu, mx_hi, 2));

        const float c_lo = __expf(m_lo - mx_lo);
        const float c_hi = __expf(m_hi - mx_hi);
        float sum_lo = 0.0f, sum_hi = 0.0f;
#pragma unroll
        for (int j = 0; j < 8; j++) {
            s[j][0] = __expf(s[j][0] - mx_lo);
            s[j][1] = __expf(s[j][1] - mx_lo);
            s[j][2] = __expf(s[j][2] - mx_hi);
            s[j][3] = __expf(s[j][3] - mx_hi);
            sum_lo += s[j][0] + s[j][1];
            sum_hi += s[j][2] + s[j][3];
        }
        sum_lo += __shfl_xor_sync(0xffffffffu, sum_lo, 1);
        sum_lo += __shfl_xor_sync(0xffffffffu, sum_lo, 2);
        sum_hi += __shfl_xor_sync(0xffffffffu, sum_hi, 1);
        sum_hi += __shfl_xor_sync(0xffffffffu, sum_hi, 2);
        l_lo = l_lo * c_lo + sum_lo;
        l_hi = l_hi * c_hi + sum_hi;
        m_lo = mx_lo;
        m_hi = mx_hi;

#pragma unroll
        for (int j = 0; j < 8; j++) {
            o[j][0] *= c_lo; o[j][1] *= c_lo;
            o[j][2] *= c_hi; o[j][3] *= c_hi;
        }

        // O += P @ V : A-frags directly from S C-frags; V B-frags via ldmatrix.x4
#pragma unroll
        for (int ks = 0; ks < 4; ks++) {
            uint32_t a[4];
            a[0] = pack_bf16(s[2 * ks][0],     s[2 * ks][1]);
            a[1] = pack_bf16(s[2 * ks][2],     s[2 * ks][3]);
            a[2] = pack_bf16(s[2 * ks + 1][0], s[2 * ks + 1][1]);
            a[3] = pack_bf16(s[2 * ks + 1][2], s[2 * ks + 1][3]);
#pragma unroll
            for (int jp = 0; jp < 4; jp++) {
                uint32_t b0, b1, b2, b3;
                ldmatrix_x4(b0, b1, b2, b3,
                            v_lm + (uint32_t)(jp * 16 * UKSTRIDE + ks * 8) * 4);
                uint32_t br0[2] = {b0, b1};
                uint32_t br1[2] = {b2, b3};
                mma_bf16(o[2 * jp],     a, br0);
                mma_bf16(o[2 * jp + 1], a, br1);
            }
        }
        __syncthreads();   // stage (kt&1) free for refill at next iteration
    }

    // Epilogue: normalize, tf32-round, write g_att (proj cp.asyncs it raw)
    const float inv_lo = 1.0f / l_lo;
    const float inv_hi = 1.0f / l_hi;
    const int n_lo = qt * 128 + wrow + qr;
#pragma unroll
    for (int j = 0; j < 8; j++) {
        const int col = h * 64 + j * 8 + 2 * qc;
        *(float2*)&g_att[((size_t)b * SEQ + n_lo) * INNER + col] =
            make_float2(tf32r(o[j][0] * inv_lo), tf32r(o[j][1] * inv_lo));
        *(float2*)&g_att[((size_t)b * SEQ + n_lo + 8) * INNER + col] =
            make_float2(tf32r(o[j][2] * inv_hi), tf32r(o[j][3] * inv_hi));
    }
}

// ---------------------------------------------------------------------------
// Kernel 3: output projection (tf32).  out = g_att @ g_w[3] + bp
// ---------------------------------------------------------------------------
__global__ __launch_bounds__(256, 2) void proj_kernel(const float* __restrict__ bp,
                                                      float* __restrict__ out) {
    extern __shared__ float smf[];
    const uint32_t su = (uint32_t)__cvta_generic_to_shared(smf);
    const float* Wp = g_w + 3 * NWF;

    const int bm = blockIdx.y * 128;
    const int bn = blockIdx.x * 128;
    const int t  = threadIdx.x;
    const int warp = t >> 5;
    const int lane = t & 31;
    const int m_base = (warp >> 1) * 32;
    const int n_base = (warp & 1) * 64;
    const int qr = lane >> 2;
    const int qc = lane & 3;

    float acc[2][8][4];
#pragma unroll
    for (int mt = 0; mt < 2; mt++)
#pragma unroll
        for (int j = 0; j < 8; j++)
#pragma unroll
            for (int e = 0; e < 4; e++) acc[mt][j][e] = 0.0f;

    gemm_fill(su, 0, 0, g_att, bm, Wp, bn, t);
    CP_COMMIT();

    for (int kt = 0; kt < INNER / 32; kt++) {
        if (kt + 1 < INNER / 32) {
            gemm_fill(su, (kt + 1) & 1, (kt + 1) * 32, g_att, bm, Wp, bn, t);
            CP_COMMIT();
            CP_WAIT1();
        } else {
            CP_WAIT0();
        }
        __syncthreads();
        gemm_compute(smf, kt & 1, m_base, n_base, qr, qc, acc);
        __syncthreads();
    }

#pragma unroll
    for (int mt = 0; mt < 2; mt++) {
#pragma unroll
        for (int j = 0; j < 8; j++) {
            const int row0 = bm + m_base + mt * 16 + qr;
            const int col0 = bn + n_base + j * 8 + 2 * qc;
            out[(size_t)row0 * DIM + col0]           = acc[mt][j][0] + bp[col0];
            out[(size_t)row0 * DIM + col0 + 1]       = acc[mt][j][1] + bp[col0 + 1];
            out[(size_t)(row0 + 8) * DIM + col0]     = acc[mt][j][2] + bp[col0];
            out[(size_t)(row0 + 8) * DIM + col0 + 1] = acc[mt][j][3] + bp[col0 + 1];
        }
    }
}

// ---------------------------------------------------------------------------
extern "C" void kernel_launch(void* const* d_in, const int* in_sizes, int n_in,
                              void* d_out, int out_size) {
    const float* x  = (const float*)d_in[0];
    const float* Wq = (const float*)d_in[1];
    const float* Wk = (const float*)d_in[2];
    const float* Wv = (const float*)d_in[3];
    const float* Wp = (const float*)d_in[4];
    const float* bp = (const float*)d_in[5];
    float* out = (float*)d_out;

    const int gemm_smem  = GEMM_SMEM_FLOATS * (int)sizeof(float);   // 71680
    const int flash_smem = FLASH_SMEM_U * (int)sizeof(uint32_t);    // 55296
    cudaFuncSetAttribute(qkv_kernel,
                         cudaFuncAttributeMaxDynamicSharedMemorySize, gemm_smem);
    cudaFuncSetAttribute(flash_kernel,
                         cudaFuncAttributeMaxDynamicSharedMemorySize, flash_smem);
    cudaFuncSetAttribute(proj_kernel,
                         cudaFuncAttributeMaxDynamicSharedMemorySize, gemm_smem);

    // 0) tf32-round x and weights into scratch
    round_kernel<<<(NXF + 4 * NWF) / 1024, 256>>>(x, Wq, Wk, Wv, Wp);

    // 1) QKV projections (tf32 MMA, bf16 outputs; V transposed)
    qkv_kernel<<<dim3(INNER / 128, MROWS / 128, 3), 256, gemm_smem>>>();

    // 2) flash attention (bf16 MMA, ldmatrix B-frags, register-resident P)
    flash_kernel<<<dim3(SEQ / 128, NH, Bb), 256, flash_smem>>>();

    // 3) output projection + bias (tf32 MMA)
    proj_kernel<<<dim3(DIM / 128, MROWS / 128), 256, gemm_smem>>>(bp, out);
}

// round 11
// speedup vs baseline: 5.5718x; 1.0178x over previous
#include <cuda_runtime.h>
#include <cuda_bf16.h>
#include <math.h>
#include <stdint.h>

// Problem constants
#define Bb     4
#define SEQ    2048
#define DIM    768
#define NH     12
#define DH     64
#define INNER  768
#define MROWS  (Bb * SEQ)   // 8192
#define NXF    (MROWS * DIM)      // 6291456 floats in x
#define NWF    (DIM * INNER)      // 589824 floats per weight

// Scratch (module-static device memory; allocation-free)
__device__ float g_x[NXF];                    // tf32-rounded x
__device__ float g_w[4 * NWF];                // tf32-rounded Wq,Wk,Wv,Wp
__device__ __align__(16) __nv_bfloat16 g_qb[Bb * NH * SEQ * DH];  // *log2e/8
__device__ __align__(16) __nv_bfloat16 g_kb[Bb * NH * SEQ * DH];  // [b][h][n][dh]
__device__ __align__(16) __nv_bfloat16 g_vt[Bb * NH * DH * SEQ];  // [b][h][dh][n]
__device__ float g_att[MROWS * INNER];        // attention out (tf32), [b*n][h*64+dh]

// ---------------------------------------------------------------------------
// Helpers
// ---------------------------------------------------------------------------
__device__ __forceinline__ float tf32r(float x) {
    uint32_t u;
    asm("cvt.rna.tf32.f32 %0, %1;" : "=r"(u) : "f"(x));
    return __uint_as_float(u);
}

__device__ __forceinline__ void mma_tf32(float d[4], const uint32_t a[4],
                                         const uint32_t b[2]) {
    asm volatile(
        "mma.sync.aligned.m16n8k8.row.col.f32.tf32.tf32.f32 "
        "{%0,%1,%2,%3}, {%4,%5,%6,%7}, {%8,%9}, {%0,%1,%2,%3};"
        : "+f"(d[0]), "+f"(d[1]), "+f"(d[2]), "+f"(d[3])
        : "r"(a[0]), "r"(a[1]), "r"(a[2]), "r"(a[3]), "r"(b[0]), "r"(b[1]));
}

__device__ __forceinline__ void mma_bf16(float d[4], const uint32_t a[4],
                                         const uint32_t b[2]) {
    asm volatile(
        "mma.sync.aligned.m16n8k16.row.col.f32.bf16.bf16.f32 "
        "{%0,%1,%2,%3}, {%4,%5,%6,%7}, {%8,%9}, {%0,%1,%2,%3};"
        : "+f"(d[0]), "+f"(d[1]), "+f"(d[2]), "+f"(d[3])
        : "r"(a[0]), "r"(a[1]), "r"(a[2]), "r"(a[3]), "r"(b[0]), "r"(b[1]));
}

// Warp-collective: load 4 8x8 b16 matrices.
__device__ __forceinline__ void ldmatrix_x4(uint32_t& r0, uint32_t& r1,
                                            uint32_t& r2, uint32_t& r3,
                                            uint32_t saddr) {
    asm volatile(
        "ldmatrix.sync.aligned.m8n8.x4.shared.b16 {%0,%1,%2,%3}, [%4];"
        : "=r"(r0), "=r"(r1), "=r"(r2), "=r"(r3) : "r"(saddr));
}

__device__ __forceinline__ uint32_t pack_bf16(float lo, float hi) {
    __nv_bfloat162 h = __floats2bfloat162_rn(lo, hi);
    return *(uint32_t*)&h;
}

__device__ __forceinline__ void cp16(uint32_t saddr, const void* gaddr) {
    asm volatile("cp.async.cg.shared.global [%0], [%1], 16;" :: "r"(saddr), "l"(gaddr));
}
#define CP_COMMIT()  asm volatile("cp.async.commit_group;")
#define CP_WAIT1()   asm volatile("cp.async.wait_group 1;" ::: "memory")
#define CP_WAIT0()   asm volatile("cp.async.wait_group 0;" ::: "memory")

// ---------------------------------------------------------------------------
// Kernel 0: round x and the 4 weight matrices to tf32 (elementwise, once).
// ---------------------------------------------------------------------------
__global__ void round_kernel(const float* __restrict__ x,
                             const float* __restrict__ Wq,
                             const float* __restrict__ Wk,
                             const float* __restrict__ Wv,
                             const float* __restrict__ Wp) {
    const int base = (blockIdx.x * 256 + threadIdx.x) * 4;
    if (base < NXF) {
        float4 v = *(const float4*)&x[base];
        v.x = tf32r(v.x); v.y = tf32r(v.y); v.z = tf32r(v.z); v.w = tf32r(v.w);
        *(float4*)&g_x[base] = v;
    } else {
        const int j = base - NXF;
        const int w = j / NWF;
        const int off = j - w * NWF;
        const float* src = (w == 0) ? Wq : (w == 1) ? Wk : (w == 2) ? Wv : Wp;
        float4 v = *(const float4*)&src[off];
        v.x = tf32r(v.x); v.y = tf32r(v.y); v.z = tf32r(v.z); v.w = tf32r(v.w);
        *(float4*)&g_w[w * NWF + off] = v;
    }
}

// ---------------------------------------------------------------------------
// GEMM smem geometry (qkv & proj): BM=128, BN=128, BK=32, 3-stage cp.async.
// ---------------------------------------------------------------------------
#define ASTRIDE   36
#define BSTRIDE   136
#define AS_STAGE  (128 * ASTRIDE)          // 4608 floats
#define BS_BASE   (3 * AS_STAGE)           // 13824
#define BS_STAGE  (32 * BSTRIDE)           // 4352
#define GEMM_SMEM_FLOATS (BS_BASE + 3 * BS_STAGE)   // 26880 -> 107520 B

__device__ __forceinline__ void gemm_fill(uint32_t su, int st, int k0,
                                          const float* __restrict__ gA, int bm,
                                          const float* __restrict__ gB, int bn,
                                          int t) {
#pragma unroll
    for (int i = 0; i < 4; i++) {
        const int lin = t + i * 256;
        const int row = lin >> 3;
        const int col = (lin & 7) * 4;
        cp16(su + (uint32_t)(st * AS_STAGE + row * ASTRIDE + col) * 4,
             &gA[(size_t)(bm + row) * DIM + k0 + col]);
    }
#pragma unroll
    for (int i = 0; i < 4; i++) {
        const int lin = t + i * 256;
        const int row = lin >> 5;
        const int col = (lin & 31) * 4;
        cp16(su + (uint32_t)(BS_BASE + st * BS_STAGE + row * BSTRIDE + col) * 4,
             &gB[(size_t)(k0 + row) * INNER + bn + col]);
    }
}

__device__ __forceinline__ void gemm_compute(const float* __restrict__ smf, int st,
                                             int m_base, int n_base, int qr, int qc,
                                             float acc[2][8][4]) {
    const uint32_t* A = (const uint32_t*)(smf + st * AS_STAGE);
    const uint32_t* Bm = (const uint32_t*)(smf + BS_BASE + st * BS_STAGE);
#pragma unroll
    for (int ks = 0; ks < 4; ks++) {
        const int kk = ks * 8;
        uint32_t a[2][4];
#pragma unroll
        for (int mt = 0; mt < 2; mt++) {
            const int row = m_base + mt * 16 + qr;
            a[mt][0] = A[row * ASTRIDE + kk + qc];
            a[mt][1] = A[(row + 8) * ASTRIDE + kk + qc];
            a[mt][2] = A[row * ASTRIDE + kk + 4 + qc];
            a[mt][3] = A[(row + 8) * ASTRIDE + kk + 4 + qc];
        }
#pragma unroll
        for (int j = 0; j < 8; j++) {
            uint32_t b[2];
            const int col = n_base + j * 8 + qr;
            b[0] = Bm[(kk + qc) * BSTRIDE + col];
            b[1] = Bm[(kk + 4 + qc) * BSTRIDE + col];
#pragma unroll
            for (int mt = 0; mt < 2; mt++) mma_tf32(acc[mt][j], a[mt], b);
        }
    }
}

// ---------------------------------------------------------------------------
// Kernel 1: fused QKV projection (tf32 MMA), bf16 outputs.
// q is scaled by log2(e)/8 so flash softmax can use exp2 directly.
// ---------------------------------------------------------------------------
#define QSCALE 0.1803368801111204f   // 0.125 * log2(e)

__global__ __launch_bounds__(256, 2) void qkv_kernel() {
    extern __shared__ float smf[];
    const uint32_t su = (uint32_t)__cvta_generic_to_shared(smf);

    const float* W;
    __nv_bfloat16* outp;
    float scale = 1.0f;
    bool transpose = false;
    if (blockIdx.z == 0)      { W = g_w;           outp = g_qb; scale = QSCALE; }
    else if (blockIdx.z == 1) { W = g_w + NWF;     outp = g_kb; }
    else                      { W = g_w + 2 * NWF; outp = g_vt; transpose = true; }

    const int bm = blockIdx.y * 128;
    const int bn = blockIdx.x * 128;
    const int t  = threadIdx.x;
    const int warp = t >> 5;
    const int lane = t & 31;
    const int m_base = (warp >> 1) * 32;
    const int n_base = (warp & 1) * 64;
    const int qr = lane >> 2;
    const int qc = lane & 3;

    float acc[2][8][4];
#pragma unroll
    for (int mt = 0; mt < 2; mt++)
#pragma unroll
        for (int j = 0; j < 8; j++)
#pragma unroll
            for (int e = 0; e < 4; e++) acc[mt][j][e] = 0.0f;

    // Prologue: fill stages 0 and 1 (tiles 0, 1)
    gemm_fill(su, 0, 0, g_x, bm, W, bn, t);
    CP_COMMIT();
    gemm_fill(su, 1, 32, g_x, bm, W, bn, t);
    CP_COMMIT();

    int cs = 0, fs = 2;
    for (int kt = 0; kt < DIM / 32; kt++) {
        if (kt + 1 < DIM / 32) { CP_WAIT1(); } else { CP_WAIT0(); }
        __syncthreads();                       // single barrier per tile
        if (kt + 2 < DIM / 32) {
            gemm_fill(su, fs, (kt + 2) * 32, g_x, bm, W, bn, t);
            CP_COMMIT();
        }
        gemm_compute(smf, cs, m_base, n_base, qr, qc, acc);
        cs = (cs == 2) ? 0 : cs + 1;
        fs = (fs == 2) ? 0 : fs + 1;
    }

    // Epilogue: bf16 scatter into head-major (or transposed for V)
#pragma unroll
    for (int mt = 0; mt < 2; mt++) {
#pragma unroll
        for (int j = 0; j < 8; j++) {
#pragma unroll
            for (int e = 0; e < 4; e++) {
                const int row = bm + m_base + mt * 16 + qr + (e >= 2 ? 8 : 0);
                const int col = bn + n_base + j * 8 + 2 * qc + (e & 1);
                const int bidx = row >> 11;
                const int n    = row & 2047;
                const int h    = col >> 6;
                const int dh   = col & 63;
                const size_t idx = transpose
                    ? ((((size_t)bidx * NH + h) * DH) + dh) * SEQ + n
                    : ((((size_t)bidx * NH + h) * SEQ) + n) * DH + dh;
                outp[idx] = __float2bfloat16(acc[mt][j][e] * scale);
            }
        }
    }
}

// ---------------------------------------------------------------------------
// Kernel 2: flash attention, bf16 m16n8k16 MMA, 3-stage cp.async K/Vt pipeline.
// One __syncthreads per KV tile. exp2-domain softmax (q pre-scaled by log2e/8).
// smem (u32): K[3][64][36], Vt[3][64][36], Ps[128][36] = 73728 B
// ---------------------------------------------------------------------------
#define UKSTRIDE   36
#define KV_STAGE_U (64 * UKSTRIDE)                 // 2304
#define VS_BASE_U  (3 * KV_STAGE_U)                // 6912
#define PS_BASE_U  (VS_BASE_U + 3 * KV_STAGE_U)    // 13824
#define FLASH_SMEM_U (PS_BASE_U + 128 * UKSTRIDE)  // 18432 -> 73728 B

__global__ __launch_bounds__(256, 2) void flash_kernel() {
    extern __shared__ uint32_t smu[];
    const uint32_t su = (uint32_t)__cvta_generic_to_shared(smu);
    uint32_t* Psu = smu + PS_BASE_U;

    const int qt = blockIdx.x;
    const int h  = blockIdx.y;
    const int b  = blockIdx.z;
    const int t  = threadIdx.x;
    const int warp = t >> 5;
    const int lane = t & 31;
    const int qr = lane >> 2;
    const int qc = lane & 3;
    const int wrow = warp * 16;

    const int lm_row = (lane & 7) + ((lane & 16) >> 1);
    const int lm_col = (lane & 8) >> 1;
    const uint32_t lm_off = (uint32_t)(lm_row * UKSTRIDE + lm_col) * 4;

    const size_t head_nd = ((size_t)b * NH + h) * SEQ * DH;
    const __nv_bfloat16* qbase  = g_qb + head_nd + (size_t)qt * 128 * DH;
    const __nv_bfloat16* kbase  = g_kb + head_nd;
    const __nv_bfloat16* vtbase = g_vt + head_nd;   // [dh][n]

    // Prologue: fill K/Vt tiles 0 (stage 0) and 1 (stage 1)
#pragma unroll
    for (int st = 0; st < 2; st++) {
        const __nv_bfloat16* ktile = kbase + (size_t)st * 64 * DH;
        const __nv_bfloat16* vtile = vtbase + (size_t)st * 64;
#pragma unroll
        for (int i = 0; i < 2; i++) {
            const int lin = t + i * 256;
            const int row = lin >> 3;
            const int ch  = lin & 7;
            cp16(su + (uint32_t)(st * KV_STAGE_U + row * UKSTRIDE + ch * 4) * 4,
                 ktile + row * DH + ch * 8);
            cp16(su + (uint32_t)(VS_BASE_U + st * KV_STAGE_U + row * UKSTRIDE + ch * 4) * 4,
                 vtile + (size_t)row * SEQ + ch * 8);
        }
        CP_COMMIT();
    }

    // Stage Q (bf16) into Ps: 128 rows x 64 bf16
#pragma unroll
    for (int i = 0; i < 4; i++) {
        const int lin = t + i * 256;
        const int row = lin >> 3;
        const int ch  = lin & 7;
        *(float4*)&Psu[row * UKSTRIDE + ch * 4] =
            *(const float4*)&qbase[row * DH + ch * 8];
    }
    __syncthreads();

    uint32_t qf[4][4];
#pragma unroll
    for (int ks = 0; ks < 4; ks++) {
        qf[ks][0] = Psu[(wrow + qr) * UKSTRIDE + ks * 8 + qc];
        qf[ks][1] = Psu[(wrow + qr + 8) * UKSTRIDE + ks * 8 + qc];
        qf[ks][2] = Psu[(wrow + qr) * UKSTRIDE + ks * 8 + 4 + qc];
        qf[ks][3] = Psu[(wrow + qr + 8) * UKSTRIDE + ks * 8 + 4 + qc];
    }

    float o[8][4];
#pragma unroll
    for (int j = 0; j < 8; j++)
#pragma unroll
        for (int e = 0; e < 4; e++) o[j][e] = 0.0f;
    float m_lo = -INFINITY, m_hi = -INFINITY, l_lo = 0.0f, l_hi = 0.0f;

    int cs = 0, fs = 2;
    for (int kt = 0; kt < SEQ / 64; kt++) {
        if (kt + 1 < SEQ / 64) { CP_WAIT1(); } else { CP_WAIT0(); }
        __syncthreads();                       // single barrier per tile
        if (kt + 2 < SEQ / 64) {
            const __nv_bfloat16* ktile = kbase + (size_t)(kt + 2) * 64 * DH;
            const __nv_bfloat16* vtile = vtbase + (size_t)(kt + 2) * 64;
#pragma unroll
            for (int i = 0; i < 2; i++) {
                const int lin = t + i * 256;
                const int row = lin >> 3;
                const int ch  = lin & 7;
                cp16(su + (uint32_t)(fs * KV_STAGE_U + row * UKSTRIDE + ch * 4) * 4,
                     ktile + row * DH + ch * 8);
                cp16(su + (uint32_t)(VS_BASE_U + fs * KV_STAGE_U + row * UKSTRIDE + ch * 4) * 4,
                     vtile + (size_t)row * SEQ + ch * 8);
            }
            CP_COMMIT();
        }

        const uint32_t k_lm = su + (uint32_t)(cs * KV_STAGE_U) * 4 + lm_off;
        const uint32_t v_lm = su + (uint32_t)(VS_BASE_U + cs * KV_STAGE_U) * 4 + lm_off;

        // S = Q @ K^T (log2-domain scores)
        float s[8][4];
#pragma unroll
        for (int j = 0; j < 8; j++)
#pragma unroll
            for (int e = 0; e < 4; e++) s[j][e] = 0.0f;
#pragma unroll
        for (int ks = 0; ks < 4; ks++) {
#pragma unroll
            for (int jp = 0; jp < 4; jp++) {
                uint32_t b0, b1, b2, b3;
                ldmatrix_x4(b0, b1, b2, b3,
                            k_lm + (uint32_t)(jp * 16 * UKSTRIDE + ks * 8) * 4);
                uint32_t br0[2] = {b0, b1};
                uint32_t br1[2] = {b2, b3};
                mma_bf16(s[2 * jp],     qf[ks], br0);
                mma_bf16(s[2 * jp + 1], qf[ks], br1);
            }
        }

        // Online softmax in exp2 domain (quad reductions)
        float mx_lo = m_lo, mx_hi = m_hi;
#pragma unroll
        for (int j = 0; j < 8; j++) {
            mx_lo = fmaxf(mx_lo, fmaxf(s[j][0], s[j][1]));
            mx_hi = fmaxf(mx_hi, fmaxf(s[j][2], s[j][3]));
        }
        mx_lo = fmaxf(mx_lo, __shfl_xor_sync(0xffffffffu, mx_lo, 1));
        mx_lo = fmaxf(mx_lo, __shfl_xor_sync(0xffffffffu, mx_lo, 2));
        mx_hi = fmaxf(mx_hi, __shfl_xor_sync(0xffffffffu, mx_hi, 1));
        mx_hi = fmaxf(mx_hi, __shfl_xor_sync(0xffffffffu, mx_hi, 2));

        const float c_lo = exp2f(m_lo - mx_lo);
        const float c_hi = exp2f(m_hi - mx_hi);
        float sum_lo = 0.0f, sum_hi = 0.0f;
#pragma unroll
        for (int j = 0; j < 8; j++) {
            s[j][0] = exp2f(s[j][0] - mx_lo);
            s[j][1] = exp2f(s[j][1] - mx_lo);
            s[j][2] = exp2f(s[j][2] - mx_hi);
            s[j][3] = exp2f(s[j][3] - mx_hi);
            sum_lo += s[j][0] + s[j][1];
            sum_hi += s[j][2] + s[j][3];
        }
        sum_lo += __shfl_xor_sync(0xffffffffu, sum_lo, 1);
        sum_lo += __shfl_xor_sync(0xffffffffu, sum_lo, 2);
        sum_hi += __shfl_xor_sync(0xffffffffu, sum_hi, 1);
        sum_hi += __shfl_xor_sync(0xffffffffu, sum_hi, 2);
        l_lo = l_lo * c_lo + sum_lo;
        l_hi = l_hi * c_hi + sum_hi;
        m_lo = mx_lo;
        m_hi = mx_hi;

#pragma unroll
        for (int j = 0; j < 8; j++) {
            o[j][0] *= c_lo; o[j][1] *= c_lo;
            o[j][2] *= c_hi; o[j][3] *= c_hi;
        }

        // O += P @ V : A-frags directly from S C-frags
#pragma unroll
        for (int ks = 0; ks < 4; ks++) {
            uint32_t a[4];
            a[0] = pack_bf16(s[2 * ks][0],     s[2 * ks][1]);
            a[1] = pack_bf16(s[2 * ks][2],     s[2 * ks][3]);
            a[2] = pack_bf16(s[2 * ks + 1][0], s[2 * ks + 1][1]);
            a[3] = pack_bf16(s[2 * ks + 1][2], s[2 * ks + 1][3]);
#pragma unroll
            for (int jp = 0; jp < 4; jp++) {
                uint32_t b0, b1, b2, b3;
                ldmatrix_x4(b0, b1, b2, b3,
                            v_lm + (uint32_t)(jp * 16 * UKSTRIDE + ks * 8) * 4);
                uint32_t br0[2] = {b0, b1};
                uint32_t br1[2] = {b2, b3};
                mma_bf16(o[2 * jp],     a, br0);
                mma_bf16(o[2 * jp + 1], a, br1);
            }
        }

        cs = (cs == 2) ? 0 : cs + 1;
        fs = (fs == 2) ? 0 : fs + 1;
    }

    // Epilogue: normalize, tf32-round, write g_att
    const float inv_lo = 1.0f / l_lo;
    const float inv_hi = 1.0f / l_hi;
    const int n_lo = qt * 128 + wrow + qr;
#pragma unroll
    for (int j = 0; j < 8; j++) {
        const int col = h * 64 + j * 8 + 2 * qc;
        *(float2*)&g_att[((size_t)b * SEQ + n_lo) * INNER + col] =
            make_float2(tf32r(o[j][0] * inv_lo), tf32r(o[j][1] * inv_lo));
        *(float2*)&g_att[((size_t)b * SEQ + n_lo + 8) * INNER + col] =
            make_float2(tf32r(o[j][2] * inv_hi), tf32r(o[j][3] * inv_hi));
    }
}

// ---------------------------------------------------------------------------
// Kernel 3: output projection (tf32).  out = g_att @ g_w[3] + bp
// ---------------------------------------------------------------------------
__global__ __launch_bounds__(256, 2) void proj_kernel(const float* __restrict__ bp,
                                                      float* __restrict__ out) {
    extern __shared__ float smf[];
    const uint32_t su = (uint32_t)__cvta_generic_to_shared(smf);
    const float* Wp = g_w + 3 * NWF;

    const int bm = blockIdx.y * 128;
    const int bn = blockIdx.x * 128;
    const int t  = threadIdx.x;
    const int warp = t >> 5;
    const int lane = t & 31;
    const int m_base = (warp >> 1) * 32;
    const int n_base = (warp & 1) * 64;
    const int qr = lane >> 2;
    const int qc = lane & 3;

    float acc[2][8][4];
#pragma unroll
    for (int mt = 0; mt < 2; mt++)
#pragma unroll
        for (int j = 0; j < 8; j++)
#pragma unroll
            for (int e = 0; e < 4; e++) acc[mt][j][e] = 0.0f;

    gemm_fill(su, 0, 0, g_att, bm, Wp, bn, t);
    CP_COMMIT();
    gemm_fill(su, 1, 32, g_att, bm, Wp, bn, t);
    CP_COMMIT();

    int cs = 0, fs = 2;
    for (int kt = 0; kt < INNER / 32; kt++) {
        if (kt + 1 < INNER / 32) { CP_WAIT1(); } else { CP_WAIT0(); }
        __syncthreads();
        if (kt + 2 < INNER / 32) {
            gemm_fill(su, fs, (kt + 2) * 32, g_att, bm, Wp, bn, t);
            CP_COMMIT();
        }
        gemm_compute(smf, cs, m_base, n_base, qr, qc, acc);
        cs = (cs == 2) ? 0 : cs + 1;
        fs = (fs == 2) ? 0 : fs + 1;
    }

#pragma unroll
    for (int mt = 0; mt < 2; mt++) {
#pragma unroll
        for (int j = 0; j < 8; j++) {
            const int row0 = bm + m_base + mt * 16 + qr;
            const int col0 = bn + n_base + j * 8 + 2 * qc;
            out[(size_t)row0 * DIM + col0]           = acc[mt][j][0] + bp[col0];
            out[(size_t)row0 * DIM + col0 + 1]       = acc[mt][j][1] + bp[col0 + 1];
            out[(size_t)(row0 + 8) * DIM + col0]     = acc[mt][j][2] + bp[col0];
            out[(size_t)(row0 + 8) * DIM + col0 + 1] = acc[mt][j][3] + bp[col0 + 1];
        }
    }
}

// ---------------------------------------------------------------------------
extern "C" void kernel_launch(void* const* d_in, const int* in_sizes, int n_in,
                              void* d_out, int out_size) {
    const float* x  = (const float*)d_in[0];
    const float* Wq = (const float*)d_in[1];
    const float* Wk = (const float*)d_in[2];
    const float* Wv = (const float*)d_in[3];
    const float* Wp = (const float*)d_in[4];
    const float* bp = (const float*)d_in[5];
    float* out = (float*)d_out;

    const int gemm_smem  = GEMM_SMEM_FLOATS * (int)sizeof(float);   // 107520
    const int flash_smem = FLASH_SMEM_U * (int)sizeof(uint32_t);    // 73728
    cudaFuncSetAttribute(qkv_kernel,
                         cudaFuncAttributeMaxDynamicSharedMemorySize, gemm_smem);
    cudaFuncSetAttribute(flash_kernel,
                         cudaFuncAttributeMaxDynamicSharedMemorySize, flash_smem);
    cudaFuncSetAttribute(proj_kernel,
                         cudaFuncAttributeMaxDynamicSharedMemorySize, gemm_smem);

    // 0) tf32-round x and weights into scratch
    round_kernel<<<(NXF + 4 * NWF) / 1024, 256>>>(x, Wq, Wk, Wv, Wp);

    // 1) QKV projections (tf32 MMA, bf16 outputs; q scaled log2e/8; V transposed)
    qkv_kernel<<<dim3(INNER / 128, MROWS / 128, 3), 256, gemm_smem>>>();

    // 2) flash attention (bf16 MMA, exp2 softmax, 3-stage pipeline)
    flash_kernel<<<dim3(SEQ / 128, NH, Bb), 256, flash_smem>>>();

    // 3) output projection + bias (tf32 MMA, 3-stage pipeline)
    proj_kernel<<<dim3(DIM / 128, MROWS / 128), 256, gemm_smem>>>(bp, out);
}

// round 12
// speedup vs baseline: 5.5732x; 1.0003x over previous
#include <cuda_runtime.h>
#include <cuda_bf16.h>
#include <math.h>
#include <stdint.h>

// Problem constants
#define Bb     4
#define SEQ    2048
#define DIM    768
#define NH     12
#define DH     64
#define INNER  768
#define MROWS  (Bb * SEQ)   // 8192
#define NXF    (MROWS * DIM)      // 6291456 floats in x
#define NWF    (DIM * INNER)      // 589824 floats per weight

// Scratch (module-static device memory; allocation-free)
__device__ float g_x[NXF];                    // tf32-rounded x
__device__ float g_w[4 * NWF];                // tf32-rounded Wq,Wk,Wv,Wp
__device__ __align__(16) __nv_bfloat16 g_qb[Bb * NH * SEQ * DH];  // *log2e/8
__device__ __align__(16) __nv_bfloat16 g_kb[Bb * NH * SEQ * DH];  // [b][h][n][dh]
__device__ __align__(16) __nv_bfloat16 g_vt[Bb * NH * DH * SEQ];  // [b][h][dh][n]
__device__ float g_att[MROWS * INNER];        // attention out (tf32), [b*n][h*64+dh]

// ---------------------------------------------------------------------------
// Helpers
// ---------------------------------------------------------------------------
__device__ __forceinline__ float tf32r(float x) {
    uint32_t u;
    asm("cvt.rna.tf32.f32 %0, %1;" : "=r"(u) : "f"(x));
    return __uint_as_float(u);
}

__device__ __forceinline__ void mma_tf32(float d[4], const uint32_t a[4],
                                         const uint32_t b[2]) {
    asm volatile(
        "mma.sync.aligned.m16n8k8.row.col.f32.tf32.tf32.f32 "
        "{%0,%1,%2,%3}, {%4,%5,%6,%7}, {%8,%9}, {%0,%1,%2,%3};"
        : "+f"(d[0]), "+f"(d[1]), "+f"(d[2]), "+f"(d[3])
        : "r"(a[0]), "r"(a[1]), "r"(a[2]), "r"(a[3]), "r"(b[0]), "r"(b[1]));
}

__device__ __forceinline__ void mma_bf16(float d[4], const uint32_t a[4],
                                         const uint32_t b[2]) {
    asm volatile(
        "mma.sync.aligned.m16n8k16.row.col.f32.bf16.bf16.f32 "
        "{%0,%1,%2,%3}, {%4,%5,%6,%7}, {%8,%9}, {%0,%1,%2,%3};"
        : "+f"(d[0]), "+f"(d[1]), "+f"(d[2]), "+f"(d[3])
        : "r"(a[0]), "r"(a[1]), "r"(a[2]), "r"(a[3]), "r"(b[0]), "r"(b[1]));
}

// Warp-collective: load 4 8x8 b16 matrices.
__device__ __forceinline__ void ldmatrix_x4(uint32_t& r0, uint32_t& r1,
                                            uint32_t& r2, uint32_t& r3,
                                            uint32_t saddr) {
    asm volatile(
        "ldmatrix.sync.aligned.m8n8.x4.shared.b16 {%0,%1,%2,%3}, [%4];"
        : "=r"(r0), "=r"(r1), "=r"(r2), "=r"(r3) : "r"(saddr));
}

__device__ __forceinline__ uint32_t pack_bf16(float lo, float hi) {
    __nv_bfloat162 h = __floats2bfloat162_rn(lo, hi);
    return *(uint32_t*)&h;
}

__device__ __forceinline__ void cp16(uint32_t saddr, const void* gaddr) {
    asm volatile("cp.async.cg.shared.global [%0], [%1], 16;" :: "r"(saddr), "l"(gaddr));
}
#define CP_COMMIT()  asm volatile("cp.async.commit_group;")
#define CP_WAIT1()   asm volatile("cp.async.wait_group 1;" ::: "memory")
#define CP_WAIT0()   asm volatile("cp.async.wait_group 0;" ::: "memory")

// ---------------------------------------------------------------------------
// Kernel 0: round x and the 4 weight matrices to tf32 (elementwise, once).
// ---------------------------------------------------------------------------
__global__ void round_kernel(const float* __restrict__ x,
                             const float* __restrict__ Wq,
                             const float* __restrict__ Wk,
                             const float* __restrict__ Wv,
                             const float* __restrict__ Wp) {
    const int base = (blockIdx.x * 256 + threadIdx.x) * 4;
    if (base < NXF) {
        float4 v = *(const float4*)&x[base];
        v.x = tf32r(v.x); v.y = tf32r(v.y); v.z = tf32r(v.z); v.w = tf32r(v.w);
        *(float4*)&g_x[base] = v;
    } else {
        const int j = base - NXF;
        const int w = j / NWF;
        const int off = j - w * NWF;
        const float* src = (w == 0) ? Wq : (w == 1) ? Wk : (w == 2) ? Wv : Wp;
        float4 v = *(const float4*)&src[off];
        v.x = tf32r(v.x); v.y = tf32r(v.y); v.z = tf32r(v.z); v.w = tf32r(v.w);
        *(float4*)&g_w[w * NWF + off] = v;
    }
}

// ---------------------------------------------------------------------------
// GEMM smem geometry (qkv & proj): BM=128, BN=128, BK=32, 3-stage cp.async.
// ---------------------------------------------------------------------------
#define ASTRIDE   36
#define BSTRIDE   136
#define AS_STAGE  (128 * ASTRIDE)          // 4608 floats
#define BS_BASE   (3 * AS_STAGE)           // 13824
#define BS_STAGE  (32 * BSTRIDE)           // 4352
#define GEMM_SMEM_FLOATS (BS_BASE + 3 * BS_STAGE)   // 26880 -> 107520 B

__device__ __forceinline__ void gemm_fill(uint32_t su, int st, int k0,
                                          const float* __restrict__ gA, int bm,
                                          const float* __restrict__ gB, int bn,
                                          int t) {
#pragma unroll
    for (int i = 0; i < 4; i++) {
        const int lin = t + i * 256;
        const int row = lin >> 3;
        const int col = (lin & 7) * 4;
        cp16(su + (uint32_t)(st * AS_STAGE + row * ASTRIDE + col) * 4,
             &gA[(size_t)(bm + row) * DIM + k0 + col]);
    }
#pragma unroll
    for (int i = 0; i < 4; i++) {
        const int lin = t + i * 256;
        const int row = lin >> 5;
        const int col = (lin & 31) * 4;
        cp16(su + (uint32_t)(BS_BASE + st * BS_STAGE + row * BSTRIDE + col) * 4,
             &gB[(size_t)(k0 + row) * INNER + bn + col]);
    }
}

__device__ __forceinline__ void gemm_compute(const float* __restrict__ smf, int st,
                                             int m_base, int n_base, int qr, int qc,
                                             float acc[2][8][4]) {
    const uint32_t* A = (const uint32_t*)(smf + st * AS_STAGE);
    const uint32_t* Bm = (const uint32_t*)(smf + BS_BASE + st * BS_STAGE);
#pragma unroll
    for (int ks = 0; ks < 4; ks++) {
        const int kk = ks * 8;
        uint32_t a[2][4];
#pragma unroll
        for (int mt = 0; mt < 2; mt++) {
            const int row = m_base + mt * 16 + qr;
            a[mt][0] = A[row * ASTRIDE + kk + qc];
            a[mt][1] = A[(row + 8) * ASTRIDE + kk + qc];
            a[mt][2] = A[row * ASTRIDE + kk + 4 + qc];
            a[mt][3] = A[(row + 8) * ASTRIDE + kk + 4 + qc];
        }
#pragma unroll
        for (int j = 0; j < 8; j++) {
            uint32_t b[2];
            const int col = n_base + j * 8 + qr;
            b[0] = Bm[(kk + qc) * BSTRIDE + col];
            b[1] = Bm[(kk + 4 + qc) * BSTRIDE + col];
#pragma unroll
            for (int mt = 0; mt < 2; mt++) mma_tf32(acc[mt][j], a[mt], b);
        }
    }
}

// ---------------------------------------------------------------------------
// Kernel 1: persistent fused QKV projection (tf32 MMA), bf16 outputs.
// Units: z*384 + bm_idx*6 + bn_idx  (bn fastest: same A rows + same W in L2)
// ---------------------------------------------------------------------------
#define QSCALE 0.1803368801111204f   // 0.125 * log2(e)
#define QKV_UNITS (3 * 64 * 6)       // 1152

__global__ __launch_bounds__(256, 2) void qkv_kernel() {
    extern __shared__ float smf[];
    const uint32_t su = (uint32_t)__cvta_generic_to_shared(smf);

    const int t  = threadIdx.x;
    const int warp = t >> 5;
    const int lane = t & 31;
    const int m_base = (warp >> 1) * 32;
    const int n_base = (warp & 1) * 64;
    const int qr = lane >> 2;
    const int qc = lane & 3;

    for (int unit = blockIdx.x; unit < QKV_UNITS; unit += gridDim.x) {
        __syncthreads();   // all warps done reading smem of previous unit

        const int z      = unit / 384;
        const int rem    = unit - z * 384;
        const int bm     = (rem / 6) * 128;
        const int bn     = (rem % 6) * 128;

        const float* W;
        __nv_bfloat16* outp;
        float scale = 1.0f;
        bool transpose = false;
        if (z == 0)      { W = g_w;           outp = g_qb; scale = QSCALE; }
        else if (z == 1) { W = g_w + NWF;     outp = g_kb; }
        else             { W = g_w + 2 * NWF; outp = g_vt; transpose = true; }

        float acc[2][8][4];
#pragma unroll
        for (int mt = 0; mt < 2; mt++)
#pragma unroll
            for (int j = 0; j < 8; j++)
#pragma unroll
                for (int e = 0; e < 4; e++) acc[mt][j][e] = 0.0f;

        gemm_fill(su, 0, 0, g_x, bm, W, bn, t);
        CP_COMMIT();
        gemm_fill(su, 1, 32, g_x, bm, W, bn, t);
        CP_COMMIT();

        int cs = 0, fs = 2;
        for (int kt = 0; kt < DIM / 32; kt++) {
            if (kt + 1 < DIM / 32) { CP_WAIT1(); } else { CP_WAIT0(); }
            __syncthreads();
            if (kt + 2 < DIM / 32) {
                gemm_fill(su, fs, (kt + 2) * 32, g_x, bm, W, bn, t);
                CP_COMMIT();
            }
            gemm_compute(smf, cs, m_base, n_base, qr, qc, acc);
            cs = (cs == 2) ? 0 : cs + 1;
            fs = (fs == 2) ? 0 : fs + 1;
        }

        // Epilogue: bf16 scatter (registers only; no smem)
#pragma unroll
        for (int mt = 0; mt < 2; mt++) {
#pragma unroll
            for (int j = 0; j < 8; j++) {
#pragma unroll
                for (int e = 0; e < 4; e++) {
                    const int row = bm + m_base + mt * 16 + qr + (e >= 2 ? 8 : 0);
                    const int col = bn + n_base + j * 8 + 2 * qc + (e & 1);
                    const int bidx = row >> 11;
                    const int n    = row & 2047;
                    const int h    = col >> 6;
                    const int dh   = col & 63;
                    const size_t idx = transpose
                        ? ((((size_t)bidx * NH + h) * DH) + dh) * SEQ + n
                        : ((((size_t)bidx * NH + h) * SEQ) + n) * DH + dh;
                    outp[idx] = __float2bfloat16(acc[mt][j][e] * scale);
                }
            }
        }
    }
}

// ---------------------------------------------------------------------------
// Kernel 2: persistent flash attention, bf16 MMA, 3-stage cp.async pipeline.
// Units: (b*NH + h)*16 + qt  (qt fastest: consecutive units share K/V head)
// ---------------------------------------------------------------------------
#define UKSTRIDE   36
#define KV_STAGE_U (64 * UKSTRIDE)                 // 2304
#define VS_BASE_U  (3 * KV_STAGE_U)                // 6912
#define PS_BASE_U  (VS_BASE_U + 3 * KV_STAGE_U)    // 13824
#define FLASH_SMEM_U (PS_BASE_U + 128 * UKSTRIDE)  // 18432 -> 73728 B
#define FLASH_UNITS (Bb * NH * (SEQ / 128))        // 768

__global__ __launch_bounds__(256, 2) void flash_kernel() {
    extern __shared__ uint32_t smu[];
    const uint32_t su = (uint32_t)__cvta_generic_to_shared(smu);
    uint32_t* Psu = smu + PS_BASE_U;

    const int t  = threadIdx.x;
    const int warp = t >> 5;
    const int lane = t & 31;
    const int qr = lane >> 2;
    const int qc = lane & 3;
    const int wrow = warp * 16;

    const int lm_row = (lane & 7) + ((lane & 16) >> 1);
    const int lm_col = (lane & 8) >> 1;
    const uint32_t lm_off = (uint32_t)(lm_row * UKSTRIDE + lm_col) * 4;

    for (int unit = blockIdx.x; unit < FLASH_UNITS; unit += gridDim.x) {
        __syncthreads();   // all warps done reading smem of previous unit

        const int qt = unit & 15;
        const int bh = unit >> 4;          // b*NH + h
        const int h  = bh % NH;
        const int b  = bh / NH;

        const size_t head_nd = ((size_t)b * NH + h) * SEQ * DH;
        const __nv_bfloat16* qbase  = g_qb + head_nd + (size_t)qt * 128 * DH;
        const __nv_bfloat16* kbase  = g_kb + head_nd;
        const __nv_bfloat16* vtbase = g_vt + head_nd;   // [dh][n]

        // Prologue: fill K/Vt tiles 0,1 (stages 0,1)
#pragma unroll
        for (int st = 0; st < 2; st++) {
            const __nv_bfloat16* ktile = kbase + (size_t)st * 64 * DH;
            const __nv_bfloat16* vtile = vtbase + (size_t)st * 64;
#pragma unroll
            for (int i = 0; i < 2; i++) {
                const int lin = t + i * 256;
                const int row = lin >> 3;
                const int ch  = lin & 7;
                cp16(su + (uint32_t)(st * KV_STAGE_U + row * UKSTRIDE + ch * 4) * 4,
                     ktile + row * DH + ch * 8);
                cp16(su + (uint32_t)(VS_BASE_U + st * KV_STAGE_U + row * UKSTRIDE + ch * 4) * 4,
                     vtile + (size_t)row * SEQ + ch * 8);
            }
            CP_COMMIT();
        }

        // Stage Q into Ps
#pragma unroll
        for (int i = 0; i < 4; i++) {
            const int lin = t + i * 256;
            const int row = lin >> 3;
            const int ch  = lin & 7;
            *(float4*)&Psu[row * UKSTRIDE + ch * 4] =
                *(const float4*)&qbase[row * DH + ch * 8];
        }
        __syncthreads();

        uint32_t qf[4][4];
#pragma unroll
        for (int ks = 0; ks < 4; ks++) {
            qf[ks][0] = Psu[(wrow + qr) * UKSTRIDE + ks * 8 + qc];
            qf[ks][1] = Psu[(wrow + qr + 8) * UKSTRIDE + ks * 8 + qc];
            qf[ks][2] = Psu[(wrow + qr) * UKSTRIDE + ks * 8 + 4 + qc];
            qf[ks][3] = Psu[(wrow + qr + 8) * UKSTRIDE + ks * 8 + 4 + qc];
        }

        float o[8][4];
#pragma unroll
        for (int j = 0; j < 8; j++)
#pragma unroll
            for (int e = 0; e < 4; e++) o[j][e] = 0.0f;
        float m_lo = -INFINITY, m_hi = -INFINITY, l_lo = 0.0f, l_hi = 0.0f;

        int cs = 0, fs = 2;
        for (int kt = 0; kt < SEQ / 64; kt++) {
            if (kt + 1 < SEQ / 64) { CP_WAIT1(); } else { CP_WAIT0(); }
            __syncthreads();
            if (kt + 2 < SEQ / 64) {
                const __nv_bfloat16* ktile = kbase + (size_t)(kt + 2) * 64 * DH;
                const __nv_bfloat16* vtile = vtbase + (size_t)(kt + 2) * 64;
#pragma unroll
                for (int i = 0; i < 2; i++) {
                    const int lin = t + i * 256;
                    const int row = lin >> 3;
                    const int ch  = lin & 7;
                    cp16(su + (uint32_t)(fs * KV_STAGE_U + row * UKSTRIDE + ch * 4) * 4,
                         ktile + row * DH + ch * 8);
                    cp16(su + (uint32_t)(VS_BASE_U + fs * KV_STAGE_U + row * UKSTRIDE + ch * 4) * 4,
                         vtile + (size_t)row * SEQ + ch * 8);
                }
                CP_COMMIT();
            }

            const uint32_t k_lm = su + (uint32_t)(cs * KV_STAGE_U) * 4 + lm_off;
            const uint32_t v_lm = su + (uint32_t)(VS_BASE_U + cs * KV_STAGE_U) * 4 + lm_off;

            // S = Q @ K^T (log2-domain scores)
            float s[8][4];
#pragma unroll
            for (int j = 0; j < 8; j++)
#pragma unroll
                for (int e = 0; e < 4; e++) s[j][e] = 0.0f;
#pragma unroll
            for (int ks = 0; ks < 4; ks++) {
#pragma unroll
                for (int jp = 0; jp < 4; jp++) {
                    uint32_t b0, b1, b2, b3;
                    ldmatrix_x4(b0, b1, b2, b3,
                                k_lm + (uint32_t)(jp * 16 * UKSTRIDE + ks * 8) * 4);
                    uint32_t br0[2] = {b0, b1};
                    uint32_t br1[2] = {b2, b3};
                    mma_bf16(s[2 * jp],     qf[ks], br0);
                    mma_bf16(s[2 * jp + 1], qf[ks], br1);
                }
            }

            // Online softmax in exp2 domain
            float mx_lo = m_lo, mx_hi = m_hi;
#pragma unroll
            for (int j = 0; j < 8; j++) {
                mx_lo = fmaxf(mx_lo, fmaxf(s[j][0], s[j][1]));
                mx_hi = fmaxf(mx_hi, fmaxf(s[j][2], s[j][3]));
            }
            mx_lo = fmaxf(mx_lo, __shfl_xor_sync(0xffffffffu, mx_lo, 1));
            mx_lo = fmaxf(mx_lo, __shfl_xor_sync(0xffffffffu, mx_lo, 2));
            mx_hi = fmaxf(mx_hi, __shfl_xor_sync(0xffffffffu, mx_hi, 1));
            mx_hi = fmaxf(mx_hi, __shfl_xor_sync(0xffffffffu, mx_hi, 2));

            const float c_lo = exp2f(m_lo - mx_lo);
            const float c_hi = exp2f(m_hi - mx_hi);
            float sum_lo = 0.0f, sum_hi = 0.0f;
#pragma unroll
            for (int j = 0; j < 8; j++) {
                s[j][0] = exp2f(s[j][0] - mx_lo);
                s[j][1] = exp2f(s[j][1] - mx_lo);
                s[j][2] = exp2f(s[j][2] - mx_hi);
                s[j][3] = exp2f(s[j][3] - mx_hi);
                sum_lo += s[j][0] + s[j][1];
                sum_hi += s[j][2] + s[j][3];
            }
            sum_lo += __shfl_xor_sync(0xffffffffu, sum_lo, 1);
            sum_lo += __shfl_xor_sync(0xffffffffu, sum_lo, 2);
            sum_hi += __shfl_xor_sync(0xffffffffu, sum_hi, 1);
            sum_hi += __shfl_xor_sync(0xffffffffu, sum_hi, 2);
            l_lo = l_lo * c_lo + sum_lo;
            l_hi = l_hi * c_hi + sum_hi;
            m_lo = mx_lo;
            m_hi = mx_hi;

#pragma unroll
            for (int j = 0; j < 8; j++) {
                o[j][0] *= c_lo; o[j][1] *= c_lo;
                o[j][2] *= c_hi; o[j][3] *= c_hi;
            }

            // O += P @ V
#pragma unroll
            for (int ks = 0; ks < 4; ks++) {
                uint32_t a[4];
                a[0] = pack_bf16(s[2 * ks][0],     s[2 * ks][1]);
                a[1] = pack_bf16(s[2 * ks][2],     s[2 * ks][3]);
                a[2] = pack_bf16(s[2 * ks + 1][0], s[2 * ks + 1][1]);
                a[3] = pack_bf16(s[2 * ks + 1][2], s[2 * ks + 1][3]);
#pragma unroll
                for (int jp = 0; jp < 4; jp++) {
                    uint32_t b0, b1, b2, b3;
                    ldmatrix_x4(b0, b1, b2, b3,
                                v_lm + (uint32_t)(jp * 16 * UKSTRIDE + ks * 8) * 4);
                    uint32_t br0[2] = {b0, b1};
                    uint32_t br1[2] = {b2, b3};
                    mma_bf16(o[2 * jp],     a, br0);
                    mma_bf16(o[2 * jp + 1], a, br1);
                }
            }

            cs = (cs == 2) ? 0 : cs + 1;
            fs = (fs == 2) ? 0 : fs + 1;
        }

        // Epilogue: normalize, tf32-round, write g_att
        const float inv_lo = 1.0f / l_lo;
        const float inv_hi = 1.0f / l_hi;
        const int n_lo = qt * 128 + wrow + qr;
#pragma unroll
        for (int j = 0; j < 8; j++) {
            const int col = h * 64 + j * 8 + 2 * qc;
            *(float2*)&g_att[((size_t)b * SEQ + n_lo) * INNER + col] =
                make_float2(tf32r(o[j][0] * inv_lo), tf32r(o[j][1] * inv_lo));
            *(float2*)&g_att[((size_t)b * SEQ + n_lo + 8) * INNER + col] =
                make_float2(tf32r(o[j][2] * inv_hi), tf32r(o[j][3] * inv_hi));
        }
    }
}

// ---------------------------------------------------------------------------
// Kernel 3: persistent output projection (tf32).  out = g_att @ g_w[3] + bp
// Units: bm_idx*6 + bn_idx  (bn fastest)
// ---------------------------------------------------------------------------
#define PROJ_UNITS (64 * 6)   // 384

__global__ __launch_bounds__(256, 2) void proj_kernel(const float* __restrict__ bp,
                                                      float* __restrict__ out) {
    extern __shared__ float smf[];
    const uint32_t su = (uint32_t)__cvta_generic_to_shared(smf);
    const float* Wp = g_w + 3 * NWF;

    const int t  = threadIdx.x;
    const int warp = t >> 5;
    const int lane = t & 31;
    const int m_base = (warp >> 1) * 32;
    const int n_base = (warp & 1) * 64;
    const int qr = lane >> 2;
    const int qc = lane & 3;

    for (int unit = blockIdx.x; unit < PROJ_UNITS; unit += gridDim.x) {
        __syncthreads();   // all warps done reading smem of previous unit

        const int bm = (unit / 6) * 128;
        const int bn = (unit % 6) * 128;

        float acc[2][8][4];
#pragma unroll
        for (int mt = 0; mt < 2; mt++)
#pragma unroll
            for (int j = 0; j < 8; j++)
#pragma unroll
                for (int e = 0; e < 4; e++) acc[mt][j][e] = 0.0f;

        gemm_fill(su, 0, 0, g_att, bm, Wp, bn, t);
        CP_COMMIT();
        gemm_fill(su, 1, 32, g_att, bm, Wp, bn, t);
        CP_COMMIT();

        int cs = 0, fs = 2;
        for (int kt = 0; kt < INNER / 32; kt++) {
            if (kt + 1 < INNER / 32) { CP_WAIT1(); } else { CP_WAIT0(); }
            __syncthreads();
            if (kt + 2 < INNER / 32) {
                gemm_fill(su, fs, (kt + 2) * 32, g_att, bm, Wp, bn, t);
                CP_COMMIT();
            }
            gemm_compute(smf, cs, m_base, n_base, qr, qc, acc);
            cs = (cs == 2) ? 0 : cs + 1;
            fs = (fs == 2) ? 0 : fs + 1;
        }

#pragma unroll
        for (int mt = 0; mt < 2; mt++) {
#pragma unroll
            for (int j = 0; j < 8; j++) {
                const int row0 = bm + m_base + mt * 16 + qr;
                const int col0 = bn + n_base + j * 8 + 2 * qc;
                out[(size_t)row0 * DIM + col0]           = acc[mt][j][0] + bp[col0];
                out[(size_t)row0 * DIM + col0 + 1]       = acc[mt][j][1] + bp[col0 + 1];
                out[(size_t)(row0 + 8) * DIM + col0]     = acc[mt][j][2] + bp[col0];
                out[(size_t)(row0 + 8) * DIM + col0 + 1] = acc[mt][j][3] + bp[col0 + 1];
            }
        }
    }
}

// ---------------------------------------------------------------------------
extern "C" void kernel_launch(void* const* d_in, const int* in_sizes, int n_in,
                              void* d_out, int out_size) {
    const float* x  = (const float*)d_in[0];
    const float* Wq = (const float*)d_in[1];
    const float* Wk = (const float*)d_in[2];
    const float* Wv = (const float*)d_in[3];
    const float* Wp = (const float*)d_in[4];
    const float* bp = (const float*)d_in[5];
    float* out = (float*)d_out;

    int dev = 0, sms = 148;
    cudaGetDevice(&dev);
    cudaDeviceGetAttribute(&sms, cudaDevAttrMultiProcessorCount, dev);
    const int slots = 2 * sms;   // 2 CTAs/SM for all three heavy kernels

    const int gemm_smem  = GEMM_SMEM_FLOATS * (int)sizeof(float);   // 107520
    const int flash_smem = FLASH_SMEM_U * (int)sizeof(uint32_t);    // 73728
    cudaFuncSetAttribute(qkv_kernel,
                         cudaFuncAttributeMaxDynamicSharedMemorySize, gemm_smem);
    cudaFuncSetAttribute(flash_kernel,
                         cudaFuncAttributeMaxDynamicSharedMemorySize, flash_smem);
    cudaFuncSetAttribute(proj_kernel,
                         cudaFuncAttributeMaxDynamicSharedMemorySize, gemm_smem);

    // 0) tf32-round x and weights into scratch
    round_kernel<<<(NXF + 4 * NWF) / 1024, 256>>>(x, Wq, Wk, Wv, Wp);

    // 1) QKV projections (persistent)
    const int g1 = (QKV_UNITS < slots) ? QKV_UNITS : slots;
    qkv_kernel<<<g1, 256, gemm_smem>>>();

    // 2) flash attention (persistent)
    const int g2 = (FLASH_UNITS < slots) ? FLASH_UNITS : slots;
    flash_kernel<<<g2, 256, flash_smem>>>();

    // 3) output projection + bias (persistent)
    const int g3 = (PROJ_UNITS < slots) ? PROJ_UNITS : slots;
    proj_kernel<<<g3, 256, gemm_smem>>>(bp, out);
}